// round 1
// baseline (speedup 1.0000x reference)
#include <cuda_runtime.h>
#include <math.h>

// Problem dims (fixed by the dataset)
#define BB 64
#define SS 1024
#define HH 512
#define AA 128
#define DD 256
#define H3 1536   // 3*HH

// ---------------- scratch (no allocations allowed -> device globals) ----------
__device__ float g_dec[BB * AA];      // dec_proj + bd + be folded
__device__ float g_scores[BB * SS];
__device__ float g_probs[BB * SS];
__device__ float g_att[BB * HH];
__device__ float g_gi[BB * H3];       // x @ W_ih^T + b_ih
__device__ float g_gh[BB * H3];       // states @ W_hh^T + b_hh

__device__ __forceinline__ float fast_tanh(float x) {
    float r;
    asm("tanh.approx.f32 %0, %1;" : "=f"(r) : "f"(x));
    return r;
}

// ---------------- K1: dec_proj[b,a] = states[b]·Wd[a] + bd[a] + be[a] ---------
__global__ void k1_decproj(const float* __restrict__ states,
                           const float* __restrict__ Wd,
                           const float* __restrict__ bd,
                           const float* __restrict__ be) {
    int b = blockIdx.x;
    __shared__ float st[HH];
    for (int i = threadIdx.x; i < HH; i += blockDim.x) st[i] = states[b * HH + i];
    __syncthreads();
    int warp = threadIdx.x >> 5, lane = threadIdx.x & 31;
    for (int a = warp; a < AA; a += 4) {   // 128 threads = 4 warps
        const float* w = Wd + a * HH;
        float sum = 0.f;
        for (int h = lane; h < HH; h += 32) sum += st[h] * w[h];
        #pragma unroll
        for (int o = 16; o; o >>= 1) sum += __shfl_xor_sync(0xffffffffu, sum, o);
        if (lane == 0) g_dec[b * AA + a] = sum + bd[a] + be[a];
    }
}

// ---------------- K2: scores[b,s] = Wv·tanh(enc[b,s]·We^T + dec[b]) + bv ------
// Tiled GEMM: per block 128 s x 128 a, K=512 in chunks of 32. 256 threads,
// 8x8 micro-tile per thread with stride-16 lane mapping (conflict-free LDS).
#define TS 128
#define KT 32
__global__ __launch_bounds__(256) void k2_scores(const float* __restrict__ enc,
                                                 const float* __restrict__ We,
                                                 const float* __restrict__ Wv,
                                                 const float* __restrict__ bv) {
    __shared__ float Es[KT][TS + 1];   // [k][s], stride 129 -> conflict-free
    __shared__ float Ws[KT][AA + 1];   // [k][a]
    const int b  = blockIdx.y;
    const int s0 = blockIdx.x * TS;
    const int tid = threadIdx.x;
    const int tx = tid & 15;    // a = tx + 16j
    const int ty = tid >> 4;    // s = ty + 16i

    float acc[8][8];
    #pragma unroll
    for (int i = 0; i < 8; i++)
        #pragma unroll
        for (int j = 0; j < 8; j++) acc[i][j] = 0.f;

    const float* encb = enc + ((size_t)b * SS + s0) * HH;

    for (int k0 = 0; k0 < HH; k0 += KT) {
        // stage tiles (coalesced 128B global reads; conflict-free smem stores)
        #pragma unroll
        for (int it = 0; it < 16; it++) {
            int idx = it * 256 + tid;
            int r = idx >> 5, k = idx & 31;
            Es[k][r] = encb[r * HH + k0 + k];
            Ws[k][r] = We[r * HH + k0 + k];
        }
        __syncthreads();
        #pragma unroll
        for (int k = 0; k < KT; k++) {
            float ev[8], wv[8];
            #pragma unroll
            for (int i = 0; i < 8; i++) ev[i] = Es[k][ty + 16 * i];
            #pragma unroll
            for (int j = 0; j < 8; j++) wv[j] = Ws[k][tx + 16 * j];
            #pragma unroll
            for (int i = 0; i < 8; i++)
                #pragma unroll
                for (int j = 0; j < 8; j++)
                    acc[i][j] = fmaf(ev[i], wv[j], acc[i][j]);
        }
        __syncthreads();
    }

    // epilogue: tanh + Wv dot, reduce over the 16 tx lanes
    float dec[8], wvv[8];
    #pragma unroll
    for (int j = 0; j < 8; j++) {
        int a = tx + 16 * j;
        dec[j] = g_dec[b * AA + a];
        wvv[j] = Wv[a];
    }
    const float bvv = bv[0];
    #pragma unroll
    for (int i = 0; i < 8; i++) {
        float p = 0.f;
        #pragma unroll
        for (int j = 0; j < 8; j++)
            p += fast_tanh(acc[i][j] + dec[j]) * wvv[j];
        #pragma unroll
        for (int o = 8; o; o >>= 1) p += __shfl_xor_sync(0xffffffffu, p, o);
        if (tx == 0) g_scores[b * SS + s0 + ty + 16 * i] = p + bvv;
    }
}

// ---------------- K3a: softmax over seq per batch -----------------------------
__global__ void k3a_softmax() {   // grid BB, block 256
    const int b = blockIdx.x, tid = threadIdx.x;
    __shared__ float red[256];
    float v[4];
    float mx = -1e30f;
    #pragma unroll
    for (int r = 0; r < 4; r++) {
        v[r] = g_scores[b * SS + tid + 256 * r];
        mx = fmaxf(mx, v[r]);
    }
    red[tid] = mx;
    __syncthreads();
    for (int o = 128; o; o >>= 1) {
        if (tid < o) red[tid] = fmaxf(red[tid], red[tid + o]);
        __syncthreads();
    }
    mx = red[0];
    __syncthreads();
    float sum = 0.f;
    #pragma unroll
    for (int r = 0; r < 4; r++) { v[r] = expf(v[r] - mx); sum += v[r]; }
    red[tid] = sum;
    __syncthreads();
    for (int o = 128; o; o >>= 1) {
        if (tid < o) red[tid] += red[tid + o];
        __syncthreads();
    }
    const float inv = 1.f / red[0];
    #pragma unroll
    for (int r = 0; r < 4; r++) g_probs[b * SS + tid + 256 * r] = v[r] * inv;
}

// ---------------- K3b: attention[b,h] = sum_s probs[b,s]*enc[b,s,h] -----------
__global__ __launch_bounds__(128) void k3b_att(const float* __restrict__ enc) {
    // grid (HH/128=4, BB)
    const int b = blockIdx.y;
    const int h = blockIdx.x * 128 + threadIdx.x;
    __shared__ float p[SS];
    for (int i = threadIdx.x; i < SS; i += 128) p[i] = g_probs[b * SS + i];
    __syncthreads();
    const float* e = enc + (size_t)b * SS * HH + h;
    float a0 = 0.f, a1 = 0.f, a2 = 0.f, a3 = 0.f;
    for (int s = 0; s < SS; s += 4) {
        a0 = fmaf(p[s + 0], e[(size_t)(s + 0) * HH], a0);
        a1 = fmaf(p[s + 1], e[(size_t)(s + 1) * HH], a1);
        a2 = fmaf(p[s + 2], e[(size_t)(s + 2) * HH], a2);
        a3 = fmaf(p[s + 3], e[(size_t)(s + 3) * HH], a3);
    }
    g_att[b * HH + h] = (a0 + a1) + (a2 + a3);
}

// ---------------- K4: gi = x@W_ih^T + b_ih ; gh = states@W_hh^T + b_hh --------
// grid 96 blocks (16 j each), 256 threads; 64 b handled in-block.
__global__ __launch_bounds__(256) void k4_gemm(const float* __restrict__ inputs,
                                               const float* __restrict__ states,
                                               const float* __restrict__ W_ih,
                                               const float* __restrict__ W_hh,
                                               const float* __restrict__ b_ih,
                                               const float* __restrict__ b_hh) {
    const int j0 = blockIdx.x * 16;
    const int tid = threadIdx.x;
    const int tx = tid & 15;    // j = j0 + tx
    const int tb = tid >> 4;    // b = tb + 16*i, i<4
    const int j = j0 + tx;
    __shared__ float Xs[64][65];
    __shared__ float Wsm[64][17];

    // ---- phase 1: K=768 over x=[inputs|attention] with W_ih ----
    float acc[4] = {0.f, 0.f, 0.f, 0.f};
    for (int k0 = 0; k0 < (DD + HH); k0 += 64) {
        #pragma unroll
        for (int it = 0; it < 16; it++) {
            int idx = it * 256 + tid;
            int bb = idx >> 6, k = idx & 63;
            int kg = k0 + k;
            Xs[k][bb] = (kg < DD) ? inputs[bb * DD + kg]
                                  : g_att[bb * HH + (kg - DD)];
        }
        #pragma unroll
        for (int it = 0; it < 4; it++) {
            int idx = it * 256 + tid;
            int jj = idx >> 6, k = idx & 63;
            Wsm[k][jj] = W_ih[(j0 + jj) * (DD + HH) + k0 + k];
        }
        __syncthreads();
        #pragma unroll
        for (int k = 0; k < 64; k++) {
            float w = Wsm[k][tx];
            #pragma unroll
            for (int i = 0; i < 4; i++)
                acc[i] = fmaf(Xs[k][tb + 16 * i], w, acc[i]);
        }
        __syncthreads();
    }
    #pragma unroll
    for (int i = 0; i < 4; i++)
        g_gi[(tb + 16 * i) * H3 + j] = acc[i] + b_ih[j];

    // ---- phase 2: K=512 over states with W_hh ----
    float acc2[4] = {0.f, 0.f, 0.f, 0.f};
    for (int k0 = 0; k0 < HH; k0 += 64) {
        #pragma unroll
        for (int it = 0; it < 16; it++) {
            int idx = it * 256 + tid;
            int bb = idx >> 6, k = idx & 63;
            Xs[k][bb] = states[bb * HH + k0 + k];
        }
        #pragma unroll
        for (int it = 0; it < 4; it++) {
            int idx = it * 256 + tid;
            int jj = idx >> 6, k = idx & 63;
            Wsm[k][jj] = W_hh[(j0 + jj) * HH + k0 + k];
        }
        __syncthreads();
        #pragma unroll
        for (int k = 0; k < 64; k++) {
            float w = Wsm[k][tx];
            #pragma unroll
            for (int i = 0; i < 4; i++)
                acc2[i] = fmaf(Xs[k][tb + 16 * i], w, acc2[i]);
        }
        __syncthreads();
    }
    #pragma unroll
    for (int i = 0; i < 4; i++)
        g_gh[(tb + 16 * i) * H3 + j] = acc2[i] + b_hh[j];
}

// ---------------- K5: GRU gates + output --------------------------------------
__global__ void k5_gru(const float* __restrict__ states, float* __restrict__ out) {
    const int b = blockIdx.x, h = threadIdx.x;   // grid 64, block 512
    const float ir = g_gi[b * H3 + h],            hr = g_gh[b * H3 + h];
    const float iz = g_gi[b * H3 + HH + h],       hz = g_gh[b * H3 + HH + h];
    const float in_ = g_gi[b * H3 + 2 * HH + h],  hn = g_gh[b * H3 + 2 * HH + h];
    const float r = 1.f / (1.f + expf(-(ir + hr)));
    const float z = 1.f / (1.f + expf(-(iz + hz)));
    const float n = tanhf(in_ + r * hn);
    out[b * HH + h] = (1.f - z) * n + z * states[b * HH + h];
}

// ---------------- launch ------------------------------------------------------
extern "C" void kernel_launch(void* const* d_in, const int* in_sizes, int n_in,
                              void* d_out, int out_size) {
    const float* encoded = (const float*)d_in[0];
    const float* inputs  = (const float*)d_in[1];
    const float* states  = (const float*)d_in[2];
    const float* We      = (const float*)d_in[3];
    const float* be      = (const float*)d_in[4];
    const float* Wd      = (const float*)d_in[5];
    const float* bd      = (const float*)d_in[6];
    const float* Wv      = (const float*)d_in[7];
    const float* bv      = (const float*)d_in[8];
    const float* W_ih    = (const float*)d_in[9];
    const float* W_hh    = (const float*)d_in[10];
    const float* b_ih    = (const float*)d_in[11];
    const float* b_hh    = (const float*)d_in[12];
    float* out = (float*)d_out;

    k1_decproj<<<BB, 128>>>(states, Wd, bd, be);
    k2_scores<<<dim3(SS / TS, BB), 256>>>(encoded, We, Wv, bv);
    k3a_softmax<<<BB, 256>>>();
    k3b_att<<<dim3(HH / 128, BB), 128>>>(encoded);
    k4_gemm<<<H3 / 16, 256>>>(inputs, states, W_ih, W_hh, b_ih, b_hh);
    k5_gru<<<BB, 512>>>(states, out);
}

// round 2
// speedup vs baseline: 3.1014x; 3.1014x over previous
#include <cuda_runtime.h>
#include <math.h>

// Problem dims (fixed by the dataset)
#define BB 64
#define SS 1024
#define HH 512
#define AA 128
#define DD 256
#define H3 1536   // 3*HH

// ---------------- scratch (no allocations allowed -> device globals) ----------
__device__ float g_dec[BB * AA];      // dec_proj + bd + be folded
__device__ float g_scores[BB * SS];
__device__ float g_probs[BB * SS];
__device__ float g_att[BB * HH];
__device__ float g_gi[BB * H3];       // x @ W_ih^T + b_ih
__device__ float g_gh[BB * H3];       // states @ W_hh^T + b_hh

__device__ __forceinline__ float fast_tanh(float x) {
    float r;
    asm("tanh.approx.f32 %0, %1;" : "=f"(r) : "f"(x));
    return r;
}

// ---------------- K1: dec_proj[b,a] = states[b]·Wd[a] + bd[a] + be[a] ---------
__global__ void k1_decproj(const float* __restrict__ states,
                           const float* __restrict__ Wd,
                           const float* __restrict__ bd,
                           const float* __restrict__ be) {
    int b = blockIdx.x;
    __shared__ float st[HH];
    for (int i = threadIdx.x; i < HH; i += blockDim.x) st[i] = states[b * HH + i];
    __syncthreads();
    int warp = threadIdx.x >> 5, lane = threadIdx.x & 31;
    for (int a = warp; a < AA; a += 4) {   // 128 threads = 4 warps
        const float* w = Wd + a * HH;
        float sum = 0.f;
        for (int h = lane; h < HH; h += 32) sum += st[h] * w[h];
        #pragma unroll
        for (int o = 16; o; o >>= 1) sum += __shfl_xor_sync(0xffffffffu, sum, o);
        if (lane == 0) g_dec[b * AA + a] = sum + bd[a] + be[a];
    }
}

// ---------------- K2: tf32 tensor-core score GEMM + fused tanh/Wv epilogue ----
// Per block: 128 s x 128 a, K=512 in chunks of 32 (cp.async double-buffered).
// 8 warps: warp_s = wid&3 (32 s rows), warp_a = wid>>2 (64 a cols).
// smem row stride = 36 floats (36 mod 32 == 4 -> all fragment LDS conflict-free).
#define K2_STRIDE 36
#define K2_TILEF  (128 * K2_STRIDE)          // floats per buffer (4608)
#define K2_SMEMF  (2 * K2_TILEF * 2 + 512)   // Es(2) + Ws(2) + dec/wv/sp
#define K2_SMEMB  (K2_SMEMF * 4)

__device__ __forceinline__ void cp_async16(float* dst, const float* src) {
    unsigned d = (unsigned)__cvta_generic_to_shared(dst);
    asm volatile("cp.async.ca.shared.global [%0], [%1], 16;\n" :: "r"(d), "l"(src));
}
__device__ __forceinline__ void cp_commit() {
    asm volatile("cp.async.commit_group;\n");
}
__device__ __forceinline__ void mma_tf32(float* d, const unsigned* a,
                                         unsigned b0, unsigned b1) {
    asm volatile(
        "mma.sync.aligned.m16n8k8.row.col.f32.tf32.tf32.f32 "
        "{%0,%1,%2,%3}, {%4,%5,%6,%7}, {%8,%9}, {%0,%1,%2,%3};\n"
        : "+f"(d[0]), "+f"(d[1]), "+f"(d[2]), "+f"(d[3])
        : "r"(a[0]), "r"(a[1]), "r"(a[2]), "r"(a[3]), "r"(b0), "r"(b1));
}

__global__ __launch_bounds__(256, 2) void k2_scores(const float* __restrict__ enc,
                                                    const float* __restrict__ We,
                                                    const float* __restrict__ Wv,
                                                    const float* __restrict__ bv) {
    extern __shared__ float sm[];
    float* Es   = sm;                        // [2][128][36]
    float* Ws   = sm + 2 * K2_TILEF;         // [2][128][36]
    float* sdec = sm + 4 * K2_TILEF;         // [128]
    float* swv  = sdec + 128;                // [128]
    float* sp   = swv + 128;                 // [2][128]

    const int b  = blockIdx.y;
    const int s0 = blockIdx.x * 128;
    const int tid = threadIdx.x;
    const int lane = tid & 31;
    const int wid = tid >> 5;
    const int warp_s = wid & 3;
    const int warp_a = wid >> 2;

    if (tid < 128) {
        sdec[tid] = g_dec[b * AA + tid];
        swv[tid]  = Wv[tid];
    }

    const float* encb = enc + ((size_t)b * SS + s0) * HH;

    float acc[2][8][4];
    #pragma unroll
    for (int f = 0; f < 2; f++)
        #pragma unroll
        for (int g = 0; g < 8; g++)
            #pragma unroll
            for (int r = 0; r < 4; r++) acc[f][g][r] = 0.f;

    // issue cp.async for chunk c into buffer buf
    auto issue = [&](int c, int buf) {
        const int k0 = c * 32;
        float* eb = Es + buf * K2_TILEF;
        float* wb = Ws + buf * K2_TILEF;
        #pragma unroll
        for (int i = 0; i < 4; i++) {
            int task = i * 256 + tid;
            int r = task >> 3, q = task & 7;             // r<128, q<8 float4s
            cp_async16(eb + r * K2_STRIDE + q * 4, encb + (size_t)r * HH + k0 + q * 4);
        }
        #pragma unroll
        for (int i = 0; i < 4; i++) {
            int task = i * 256 + tid;
            int r = task >> 3, q = task & 7;
            cp_async16(wb + r * K2_STRIDE + q * 4, We + (size_t)r * HH + k0 + q * 4);
        }
        cp_commit();
    };

    issue(0, 0);
    for (int c = 0; c < 16; c++) {
        if (c < 15) issue(c + 1, (c + 1) & 1);
        if (c < 15) asm volatile("cp.async.wait_group 1;\n");
        else        asm volatile("cp.async.wait_group 0;\n");
        __syncthreads();

        const float* eb = Es + (c & 1) * K2_TILEF;
        const float* wb = Ws + (c & 1) * K2_TILEF;
        #pragma unroll
        for (int kk = 0; kk < 4; kk++) {
            const int kc = kk * 8 + (lane & 3);
            unsigned a[2][4];
            #pragma unroll
            for (int f = 0; f < 2; f++) {
                const int r = warp_s * 32 + f * 16 + (lane >> 2);
                a[f][0] = __float_as_uint(eb[r * K2_STRIDE + kc]);
                a[f][1] = __float_as_uint(eb[(r + 8) * K2_STRIDE + kc]);
                a[f][2] = __float_as_uint(eb[r * K2_STRIDE + kc + 4]);
                a[f][3] = __float_as_uint(eb[(r + 8) * K2_STRIDE + kc + 4]);
            }
            #pragma unroll
            for (int g = 0; g < 8; g++) {
                const int ra = warp_a * 64 + g * 8 + (lane >> 2);
                unsigned b0 = __float_as_uint(wb[ra * K2_STRIDE + kc]);
                unsigned b1 = __float_as_uint(wb[ra * K2_STRIDE + kc + 4]);
                mma_tf32(acc[0][g], a[0], b0, b1);
                mma_tf32(acc[1][g], a[1], b0, b1);
            }
        }
        __syncthreads();
    }

    // epilogue: tanh(acc + dec) * wv, reduce over a
    #pragma unroll
    for (int f = 0; f < 2; f++) {
        float pl = 0.f, ph = 0.f;
        #pragma unroll
        for (int g = 0; g < 8; g++) {
            const int a0 = warp_a * 64 + g * 8 + (lane & 3) * 2;
            const float d0 = sdec[a0], d1 = sdec[a0 + 1];
            const float w0 = swv[a0],  w1 = swv[a0 + 1];
            pl += fast_tanh(acc[f][g][0] + d0) * w0 + fast_tanh(acc[f][g][1] + d1) * w1;
            ph += fast_tanh(acc[f][g][2] + d0) * w0 + fast_tanh(acc[f][g][3] + d1) * w1;
        }
        pl += __shfl_xor_sync(0xffffffffu, pl, 1);
        pl += __shfl_xor_sync(0xffffffffu, pl, 2);
        ph += __shfl_xor_sync(0xffffffffu, ph, 1);
        ph += __shfl_xor_sync(0xffffffffu, ph, 2);
        if ((lane & 3) == 0) {
            const int sl = warp_s * 32 + f * 16 + (lane >> 2);
            sp[warp_a * 128 + sl]     = pl;
            sp[warp_a * 128 + sl + 8] = ph;
        }
    }
    __syncthreads();
    if (tid < 128)
        g_scores[b * SS + s0 + tid] = sp[tid] + sp[128 + tid] + bv[0];
}

// ---------------- K3a: softmax over seq per batch (+ zero g_att) --------------
__global__ void k3a_softmax() {   // grid BB, block 256
    const int b = blockIdx.x, tid = threadIdx.x;
    // zero attention accumulator for this batch (consumed by k3b atomics)
    for (int i = tid; i < HH; i += 256) g_att[b * HH + i] = 0.f;

    __shared__ float red[256];
    float v[4];
    float mx = -1e30f;
    #pragma unroll
    for (int r = 0; r < 4; r++) {
        v[r] = g_scores[b * SS + tid + 256 * r];
        mx = fmaxf(mx, v[r]);
    }
    red[tid] = mx;
    __syncthreads();
    for (int o = 128; o; o >>= 1) {
        if (tid < o) red[tid] = fmaxf(red[tid], red[tid + o]);
        __syncthreads();
    }
    mx = red[0];
    __syncthreads();
    float sum = 0.f;
    #pragma unroll
    for (int r = 0; r < 4; r++) { v[r] = expf(v[r] - mx); sum += v[r]; }
    red[tid] = sum;
    __syncthreads();
    for (int o = 128; o; o >>= 1) {
        if (tid < o) red[tid] += red[tid + o];
        __syncthreads();
    }
    const float inv = 1.f / red[0];
    #pragma unroll
    for (int r = 0; r < 4; r++) g_probs[b * SS + tid + 256 * r] = v[r] * inv;
}

// ---------------- K3b: attention[b,h] += sum_s probs[b,s]*enc[b,s,h] ----------
// grid (HH/128=4, SS/256=4, BB) = 1024 blocks, 256 threads, float4 loads.
__global__ __launch_bounds__(256) void k3b_att(const float* __restrict__ enc) {
    const int b  = blockIdx.z;
    const int sb = blockIdx.y;
    const int hb = blockIdx.x;
    const int lane = threadIdx.x & 31;   // h quad
    const int srow = threadIdx.x >> 5;   // 0..7
    const float* e = enc + ((size_t)b * SS + sb * 256 + srow) * HH + hb * 128 + lane * 4;
    const float* pr = g_probs + b * SS + sb * 256 + srow;

    float4 a0 = {0.f, 0.f, 0.f, 0.f}, a1 = {0.f, 0.f, 0.f, 0.f};
    #pragma unroll 4
    for (int i = 0; i < 32; i += 2) {
        const float p0 = pr[i * 8];
        const float p1 = pr[(i + 1) * 8];
        const float4 v0 = *(const float4*)(e + (size_t)i * 8 * HH);
        const float4 v1 = *(const float4*)(e + (size_t)(i + 1) * 8 * HH);
        a0.x = fmaf(p0, v0.x, a0.x); a0.y = fmaf(p0, v0.y, a0.y);
        a0.z = fmaf(p0, v0.z, a0.z); a0.w = fmaf(p0, v0.w, a0.w);
        a1.x = fmaf(p1, v1.x, a1.x); a1.y = fmaf(p1, v1.y, a1.y);
        a1.z = fmaf(p1, v1.z, a1.z); a1.w = fmaf(p1, v1.w, a1.w);
    }
    a0.x += a1.x; a0.y += a1.y; a0.z += a1.z; a0.w += a1.w;

    __shared__ float red[8][32][4];
    red[srow][lane][0] = a0.x;
    red[srow][lane][1] = a0.y;
    red[srow][lane][2] = a0.z;
    red[srow][lane][3] = a0.w;
    __syncthreads();
    if (threadIdx.x < 128) {
        const int l = threadIdx.x & 31;
        const int comp = threadIdx.x >> 5;
        float s = 0.f;
        #pragma unroll
        for (int r = 0; r < 8; r++) s += red[r][l][comp];
        atomicAdd(&g_att[b * HH + hb * 128 + l * 4 + comp], s);
    }
}

// ---------------- K4: gi = x@W_ih^T + b_ih ; gh = states@W_hh^T + b_hh --------
__global__ __launch_bounds__(256) void k4_gemm(const float* __restrict__ inputs,
                                               const float* __restrict__ states,
                                               const float* __restrict__ W_ih,
                                               const float* __restrict__ W_hh,
                                               const float* __restrict__ b_ih,
                                               const float* __restrict__ b_hh) {
    const int j0 = blockIdx.x * 16;
    const int tid = threadIdx.x;
    const int tx = tid & 15;    // j = j0 + tx
    const int tb = tid >> 4;    // b = tb + 16*i, i<4
    const int j = j0 + tx;
    __shared__ float Xs[64][65];
    __shared__ float Wsm[64][17];

    float acc[4] = {0.f, 0.f, 0.f, 0.f};
    for (int k0 = 0; k0 < (DD + HH); k0 += 64) {
        #pragma unroll
        for (int it = 0; it < 16; it++) {
            int idx = it * 256 + tid;
            int bb = idx >> 6, k = idx & 63;
            int kg = k0 + k;
            Xs[k][bb] = (kg < DD) ? inputs[bb * DD + kg]
                                  : g_att[bb * HH + (kg - DD)];
        }
        #pragma unroll
        for (int it = 0; it < 4; it++) {
            int idx = it * 256 + tid;
            int jj = idx >> 6, k = idx & 63;
            Wsm[k][jj] = W_ih[(j0 + jj) * (DD + HH) + k0 + k];
        }
        __syncthreads();
        #pragma unroll
        for (int k = 0; k < 64; k++) {
            float w = Wsm[k][tx];
            #pragma unroll
            for (int i = 0; i < 4; i++)
                acc[i] = fmaf(Xs[k][tb + 16 * i], w, acc[i]);
        }
        __syncthreads();
    }
    #pragma unroll
    for (int i = 0; i < 4; i++)
        g_gi[(tb + 16 * i) * H3 + j] = acc[i] + b_ih[j];

    float acc2[4] = {0.f, 0.f, 0.f, 0.f};
    for (int k0 = 0; k0 < HH; k0 += 64) {
        #pragma unroll
        for (int it = 0; it < 16; it++) {
            int idx = it * 256 + tid;
            int bb = idx >> 6, k = idx & 63;
            Xs[k][bb] = states[bb * HH + k0 + k];
        }
        #pragma unroll
        for (int it = 0; it < 4; it++) {
            int idx = it * 256 + tid;
            int jj = idx >> 6, k = idx & 63;
            Wsm[k][jj] = W_hh[(j0 + jj) * HH + k0 + k];
        }
        __syncthreads();
        #pragma unroll
        for (int k = 0; k < 64; k++) {
            float w = Wsm[k][tx];
            #pragma unroll
            for (int i = 0; i < 4; i++)
                acc2[i] = fmaf(Xs[k][tb + 16 * i], w, acc2[i]);
        }
        __syncthreads();
    }
    #pragma unroll
    for (int i = 0; i < 4; i++)
        g_gh[(tb + 16 * i) * H3 + j] = acc2[i] + b_hh[j];
}

// ---------------- K5: GRU gates + output --------------------------------------
__global__ void k5_gru(const float* __restrict__ states, float* __restrict__ out) {
    const int b = blockIdx.x, h = threadIdx.x;   // grid 64, block 512
    const float ir = g_gi[b * H3 + h],            hr = g_gh[b * H3 + h];
    const float iz = g_gi[b * H3 + HH + h],       hz = g_gh[b * H3 + HH + h];
    const float in_ = g_gi[b * H3 + 2 * HH + h],  hn = g_gh[b * H3 + 2 * HH + h];
    const float r = 1.f / (1.f + expf(-(ir + hr)));
    const float z = 1.f / (1.f + expf(-(iz + hz)));
    const float n = tanhf(in_ + r * hn);
    out[b * HH + h] = (1.f - z) * n + z * states[b * HH + h];
}

// ---------------- launch ------------------------------------------------------
extern "C" void kernel_launch(void* const* d_in, const int* in_sizes, int n_in,
                              void* d_out, int out_size) {
    const float* encoded = (const float*)d_in[0];
    const float* inputs  = (const float*)d_in[1];
    const float* states  = (const float*)d_in[2];
    const float* We      = (const float*)d_in[3];
    const float* be      = (const float*)d_in[4];
    const float* Wd      = (const float*)d_in[5];
    const float* bd      = (const float*)d_in[6];
    const float* Wv      = (const float*)d_in[7];
    const float* bv      = (const float*)d_in[8];
    const float* W_ih    = (const float*)d_in[9];
    const float* W_hh    = (const float*)d_in[10];
    const float* b_ih    = (const float*)d_in[11];
    const float* b_hh    = (const float*)d_in[12];
    float* out = (float*)d_out;

    cudaFuncSetAttribute(k2_scores, cudaFuncAttributeMaxDynamicSharedMemorySize,
                         K2_SMEMB);

    k1_decproj<<<BB, 128>>>(states, Wd, bd, be);
    k2_scores<<<dim3(SS / 128, BB), 256, K2_SMEMB>>>(encoded, We, Wv, bv);
    k3a_softmax<<<BB, 256>>>();
    k3b_att<<<dim3(HH / 128, SS / 256, BB), 256>>>(encoded);
    k4_gemm<<<H3 / 16, 256>>>(inputs, states, W_ih, W_hh, b_ih, b_hh);
    k5_gru<<<BB, 512>>>(states, out);
}

// round 4
// speedup vs baseline: 3.3889x; 1.0927x over previous
#include <cuda_runtime.h>
#include <cuda_bf16.h>
#include <math.h>
#include <cstdint>

// Problem dims (fixed by the dataset)
#define BB 64
#define SS 1024
#define HH 512
#define AA 128
#define DD 256
#define H3 1536   // 3*HH

// ---------------- scratch (no allocations allowed -> device globals) ----------
__device__ float g_dec[BB * AA];
__device__ float g_scores[BB * SS];
__device__ float g_probs[BB * SS];
__device__ float g_att[BB * HH];
__device__ float g_gi[BB * H3];
__device__ float g_gh[BB * H3];
__device__ __align__(16) uint32_t g_We_bf[AA * HH / 2];   // We as bf16x2, [a][k]

__device__ __forceinline__ float fast_tanh(float x) {
    float r;
    asm("tanh.approx.f32 %0, %1;" : "=f"(r) : "f"(x));
    return r;
}
__device__ __forceinline__ uint32_t smem_u32(const void* p) {
    uint32_t a;
    asm("{ .reg .u64 t; cvta.to.shared.u64 t, %1; cvt.u32.u64 %0, t; }"
        : "=r"(a) : "l"(p));
    return a;
}
// pack two floats -> bf16x2 (lo = x, hi = y)
__device__ __forceinline__ uint32_t pack_bf(float x, float y) {
    uint32_t r;
    asm("cvt.rn.bf16x2.f32 %0, %1, %2;" : "=r"(r) : "f"(y), "f"(x));
    return r;
}

// ---------------- K0: convert We to bf16 once ---------------------------------
__global__ void k0_convW(const float* __restrict__ We) {
    const int base = (blockIdx.x * 256 + threadIdx.x) * 4;
    const float2* W2 = (const float2*)We;
    #pragma unroll
    for (int i = 0; i < 4; i++) {
        float2 v = W2[base + i];
        g_We_bf[base + i] = pack_bf(v.x, v.y);
    }
}

// ---------------- K1: dec_proj[b,a] = states[b]·Wd[a] + bd[a] + be[a] ---------
__global__ void k1_decproj(const float* __restrict__ states,
                           const float* __restrict__ Wd,
                           const float* __restrict__ bd,
                           const float* __restrict__ be) {
    int b = blockIdx.x;
    __shared__ float st[HH];
    for (int i = threadIdx.x; i < HH; i += blockDim.x) st[i] = states[b * HH + i];
    __syncthreads();
    int warp = threadIdx.x >> 5, lane = threadIdx.x & 31;
    for (int a = warp; a < AA; a += 4) {
        const float* w = Wd + a * HH;
        float sum = 0.f;
        for (int h = lane; h < HH; h += 32) sum += st[h] * w[h];
        #pragma unroll
        for (int o = 16; o; o >>= 1) sum += __shfl_xor_sync(0xffffffffu, sum, o);
        if (lane == 0) g_dec[b * AA + a] = sum + bd[a] + be[a];
    }
}

// ======= K2: bf16 mma.sync score GEMM (ldmatrix + SW128) + fused epilogue =====
// Block: 128 s x 128 a, K=512 in 8 chunks of 64. Tiles in smem as bf16,
// 128 B/row, SW128 swizzle at 16B granularity. 8 warps: warp_s=wid&3 (32 rows),
// warp_a=wid>>2 (64 cols). E staged LDG.128->cvt->STS.128; W staged cp.async.
#define K2_TILEB 16384                 // 128 rows * 128 bytes
#define K2_E_OFF 0
#define K2_W_OFF (2 * K2_TILEB)        // 32768
#define K2_SMEMB (4 * K2_TILEB + 2048) // + sdec/swv/sp

__device__ __forceinline__ void cp16(uint32_t daddr, const void* src) {
    asm volatile("cp.async.cg.shared.global [%0], [%1], 16;" :: "r"(daddr), "l"(src));
}
__device__ __forceinline__ void cp_commit() {
    asm volatile("cp.async.commit_group;" ::: "memory");
}
__device__ __forceinline__ void ldsm4(uint32_t* r, uint32_t addr) {
    asm volatile("ldmatrix.sync.aligned.m8n8.x4.shared.b16 {%0,%1,%2,%3}, [%4];"
                 : "=r"(r[0]), "=r"(r[1]), "=r"(r[2]), "=r"(r[3]) : "r"(addr));
}
__device__ __forceinline__ void mma_bf16(float* d, const uint32_t* a,
                                         uint32_t b0, uint32_t b1) {
    asm volatile(
        "mma.sync.aligned.m16n8k16.row.col.f32.bf16.bf16.f32 "
        "{%0,%1,%2,%3}, {%4,%5,%6,%7}, {%8,%9}, {%0,%1,%2,%3};"
        : "+f"(d[0]), "+f"(d[1]), "+f"(d[2]), "+f"(d[3])
        : "r"(a[0]), "r"(a[1]), "r"(a[2]), "r"(a[3]), "r"(b0), "r"(b1));
}

__global__ __launch_bounds__(256, 2) void k2_scores(const float* __restrict__ enc,
                                                    const float* __restrict__ Wv,
                                                    const float* __restrict__ bv) {
    extern __shared__ float sm[];
    const uint32_t smem_base = smem_u32(sm);
    float* sdec = sm + 16384;   // byte 65536
    float* swv  = sm + 16512;
    float* sp   = sm + 16640;   // 2*128 floats

    const int b  = blockIdx.y;
    const int s0 = blockIdx.x * 128;
    const int tid = threadIdx.x;
    const int lane = tid & 31;
    const int wid = tid >> 5;
    const int warp_s = wid & 3;
    const int warp_a = wid >> 2;
    const int ms = warp_s * 32;
    const int na = warp_a * 64;

    if (tid < 128) {
        sdec[tid] = g_dec[b * AA + tid];
        swv[tid]  = Wv[tid];
    }

    const float* encb = enc + ((size_t)b * SS + s0) * HH;
    const int r_st  = tid >> 3;            // staging row for i=0 (0..31)
    const int sg_st = tid & 7;             // staging 16B segment

    float acc[2][8][4];
    #pragma unroll
    for (int f = 0; f < 2; f++)
        #pragma unroll
        for (int g = 0; g < 8; g++)
            #pragma unroll
            for (int q = 0; q < 4; q++) acc[f][g][q] = 0.f;

    float4 er[8];
    // E loader: 4 tasks/thread, task (r, seg): 8 floats from enc
    auto ldE = [&](int c) {
        #pragma unroll
        for (int i = 0; i < 4; i++) {
            const int r = r_st + i * 32;
            const float* src = encb + (size_t)r * HH + c * 64 + sg_st * 8;
            er[2 * i]     = *(const float4*)src;
            er[2 * i + 1] = *(const float4*)(src + 4);
        }
    };
    auto stsE = [&](int buf) {
        #pragma unroll
        for (int i = 0; i < 4; i++) {
            const int r = r_st + i * 32;
            const uint32_t dst = smem_base + K2_E_OFF + buf * K2_TILEB
                               + r * 128 + ((sg_st ^ (r & 7)) << 4);
            uint32_t u0 = pack_bf(er[2 * i].x, er[2 * i].y);
            uint32_t u1 = pack_bf(er[2 * i].z, er[2 * i].w);
            uint32_t u2 = pack_bf(er[2 * i + 1].x, er[2 * i + 1].y);
            uint32_t u3 = pack_bf(er[2 * i + 1].z, er[2 * i + 1].w);
            asm volatile("st.shared.v4.b32 [%0], {%1,%2,%3,%4};"
                         :: "r"(dst), "r"(u0), "r"(u1), "r"(u2), "r"(u3));
        }
    };
    auto issueW = [&](int c) {
        const int buf = c & 1;
        #pragma unroll
        for (int i = 0; i < 4; i++) {
            const int r = r_st + i * 32;
            const uint32_t dst = smem_base + K2_W_OFF + buf * K2_TILEB
                               + r * 128 + ((sg_st ^ (r & 7)) << 4);
            const char* src = (const char*)g_We_bf + r * 1024 + c * 128 + sg_st * 16;
            cp16(dst, src);
        }
        cp_commit();
    };

    // prologue
    ldE(0);
    issueW(0);
    stsE(0);

    #pragma unroll
    for (int c = 0; c < 8; c++) {
        if (c < 7) { ldE(c + 1); issueW(c + 1); }
        if (c < 7) asm volatile("cp.async.wait_group 1;" ::: "memory");
        else       asm volatile("cp.async.wait_group 0;" ::: "memory");
        __syncthreads();

        const uint32_t Eb = smem_base + K2_E_OFF + (c & 1) * K2_TILEB;
        const uint32_t Wb = smem_base + K2_W_OFF + (c & 1) * K2_TILEB;
        #pragma unroll
        for (int ks = 0; ks < 4; ks++) {
            uint32_t afr[2][4];
            #pragma unroll
            for (int f = 0; f < 2; f++) {
                const int row = ms + f * 16 + (lane & 15);
                const int seg = ks * 2 + (lane >> 4);
                ldsm4(afr[f], Eb + row * 128 + ((seg ^ (row & 7)) << 4));
            }
            #pragma unroll
            for (int g2 = 0; g2 < 4; g2++) {
                const int row = na + g2 * 16 + ((lane >> 4) << 3) + (lane & 7);
                const int seg = ks * 2 + ((lane >> 3) & 1);
                uint32_t bfr[4];
                ldsm4(bfr, Wb + row * 128 + ((seg ^ (row & 7)) << 4));
                mma_bf16(acc[0][2 * g2],     afr[0], bfr[0], bfr[1]);
                mma_bf16(acc[0][2 * g2 + 1], afr[0], bfr[2], bfr[3]);
                mma_bf16(acc[1][2 * g2],     afr[1], bfr[0], bfr[1]);
                mma_bf16(acc[1][2 * g2 + 1], afr[1], bfr[2], bfr[3]);
            }
        }
        if (c < 7) stsE((c + 1) & 1);
        __syncthreads();
    }

    // epilogue: tanh(acc + dec) * wv, reduce over a
    #pragma unroll
    for (int f = 0; f < 2; f++) {
        float pl = 0.f, ph = 0.f;
        #pragma unroll
        for (int g = 0; g < 8; g++) {
            const int a0 = warp_a * 64 + g * 8 + (lane & 3) * 2;
            const float d0 = sdec[a0], d1 = sdec[a0 + 1];
            const float w0 = swv[a0],  w1 = swv[a0 + 1];
            pl += fast_tanh(acc[f][g][0] + d0) * w0 + fast_tanh(acc[f][g][1] + d1) * w1;
            ph += fast_tanh(acc[f][g][2] + d0) * w0 + fast_tanh(acc[f][g][3] + d1) * w1;
        }
        pl += __shfl_xor_sync(0xffffffffu, pl, 1);
        pl += __shfl_xor_sync(0xffffffffu, pl, 2);
        ph += __shfl_xor_sync(0xffffffffu, ph, 1);
        ph += __shfl_xor_sync(0xffffffffu, ph, 2);
        if ((lane & 3) == 0) {
            const int sl = ms + f * 16 + (lane >> 2);
            sp[warp_a * 128 + sl]     = pl;
            sp[warp_a * 128 + sl + 8] = ph;
        }
    }
    __syncthreads();
    if (tid < 128)
        g_scores[b * SS + s0 + tid] = sp[tid] + sp[128 + tid] + bv[0];
}

// ---------------- K3a: softmax over seq per batch (+ zero g_att) --------------
__global__ void k3a_softmax() {
    const int b = blockIdx.x, tid = threadIdx.x;
    for (int i = tid; i < HH; i += 256) g_att[b * HH + i] = 0.f;

    __shared__ float red[256];
    float v[4];
    float mx = -1e30f;
    #pragma unroll
    for (int r = 0; r < 4; r++) {
        v[r] = g_scores[b * SS + tid + 256 * r];
        mx = fmaxf(mx, v[r]);
    }
    red[tid] = mx;
    __syncthreads();
    for (int o = 128; o; o >>= 1) {
        if (tid < o) red[tid] = fmaxf(red[tid], red[tid + o]);
        __syncthreads();
    }
    mx = red[0];
    __syncthreads();
    float sum = 0.f;
    #pragma unroll
    for (int r = 0; r < 4; r++) { v[r] = expf(v[r] - mx); sum += v[r]; }
    red[tid] = sum;
    __syncthreads();
    for (int o = 128; o; o >>= 1) {
        if (tid < o) red[tid] += red[tid + o];
        __syncthreads();
    }
    const float inv = 1.f / red[0];
    #pragma unroll
    for (int r = 0; r < 4; r++) g_probs[b * SS + tid + 256 * r] = v[r] * inv;
}

// ---------------- K3b: attention[b,h] += sum_s probs[b,s]*enc[b,s,h] ----------
__global__ __launch_bounds__(256) void k3b_att(const float* __restrict__ enc) {
    const int b  = blockIdx.z;
    const int sb = blockIdx.y;
    const int hb = blockIdx.x;
    const int lane = threadIdx.x & 31;
    const int srow = threadIdx.x >> 5;
    const float* e = enc + ((size_t)b * SS + sb * 256 + srow) * HH + hb * 128 + lane * 4;
    const float* pr = g_probs + b * SS + sb * 256 + srow;

    float4 a0 = {0.f, 0.f, 0.f, 0.f}, a1 = {0.f, 0.f, 0.f, 0.f};
    #pragma unroll 4
    for (int i = 0; i < 32; i += 2) {
        const float p0 = pr[i * 8];
        const float p1 = pr[(i + 1) * 8];
        const float4 v0 = *(const float4*)(e + (size_t)i * 8 * HH);
        const float4 v1 = *(const float4*)(e + (size_t)(i + 1) * 8 * HH);
        a0.x = fmaf(p0, v0.x, a0.x); a0.y = fmaf(p0, v0.y, a0.y);
        a0.z = fmaf(p0, v0.z, a0.z); a0.w = fmaf(p0, v0.w, a0.w);
        a1.x = fmaf(p1, v1.x, a1.x); a1.y = fmaf(p1, v1.y, a1.y);
        a1.z = fmaf(p1, v1.z, a1.z); a1.w = fmaf(p1, v1.w, a1.w);
    }
    a0.x += a1.x; a0.y += a1.y; a0.z += a1.z; a0.w += a1.w;

    __shared__ float red[8][32][4];
    red[srow][lane][0] = a0.x;
    red[srow][lane][1] = a0.y;
    red[srow][lane][2] = a0.z;
    red[srow][lane][3] = a0.w;
    __syncthreads();
    if (threadIdx.x < 128) {
        const int l = threadIdx.x & 31;
        const int comp = threadIdx.x >> 5;
        float s = 0.f;
        #pragma unroll
        for (int r = 0; r < 8; r++) s += red[r][l][comp];
        atomicAdd(&g_att[b * HH + hb * 128 + l * 4 + comp], s);
    }
}

// ---------------- K4: gi = x@W_ih^T + b_ih ; gh = states@W_hh^T + b_hh --------
__global__ __launch_bounds__(256) void k4_gemm(const float* __restrict__ inputs,
                                               const float* __restrict__ states,
                                               const float* __restrict__ W_ih,
                                               const float* __restrict__ W_hh,
                                               const float* __restrict__ b_ih,
                                               const float* __restrict__ b_hh) {
    const int j0 = blockIdx.x * 16;
    const int tid = threadIdx.x;
    const int tx = tid & 15;
    const int tb = tid >> 4;
    const int j = j0 + tx;
    __shared__ float Xs[64][65];
    __shared__ float Wsm[64][17];

    float acc[4] = {0.f, 0.f, 0.f, 0.f};
    for (int k0 = 0; k0 < (DD + HH); k0 += 64) {
        #pragma unroll
        for (int it = 0; it < 16; it++) {
            int idx = it * 256 + tid;
            int bb = idx >> 6, k = idx & 63;
            int kg = k0 + k;
            Xs[k][bb] = (kg < DD) ? inputs[bb * DD + kg]
                                  : g_att[bb * HH + (kg - DD)];
        }
        #pragma unroll
        for (int it = 0; it < 4; it++) {
            int idx = it * 256 + tid;
            int jj = idx >> 6, k = idx & 63;
            Wsm[k][jj] = W_ih[(j0 + jj) * (DD + HH) + k0 + k];
        }
        __syncthreads();
        #pragma unroll
        for (int k = 0; k < 64; k++) {
            float w = Wsm[k][tx];
            #pragma unroll
            for (int i = 0; i < 4; i++)
                acc[i] = fmaf(Xs[k][tb + 16 * i], w, acc[i]);
        }
        __syncthreads();
    }
    #pragma unroll
    for (int i = 0; i < 4; i++)
        g_gi[(tb + 16 * i) * H3 + j] = acc[i] + b_ih[j];

    float acc2[4] = {0.f, 0.f, 0.f, 0.f};
    for (int k0 = 0; k0 < HH; k0 += 64) {
        #pragma unroll
        for (int it = 0; it < 16; it++) {
            int idx = it * 256 + tid;
            int bb = idx >> 6, k = idx & 63;
            Xs[k][bb] = states[bb * HH + k0 + k];
        }
        #pragma unroll
        for (int it = 0; it < 4; it++) {
            int idx = it * 256 + tid;
            int jj = idx >> 6, k = idx & 63;
            Wsm[k][jj] = W_hh[(j0 + jj) * HH + k0 + k];
        }
        __syncthreads();
        #pragma unroll
        for (int k = 0; k < 64; k++) {
            float w = Wsm[k][tx];
            #pragma unroll
            for (int i = 0; i < 4; i++)
                acc2[i] = fmaf(Xs[k][tb + 16 * i], w, acc2[i]);
        }
        __syncthreads();
    }
    #pragma unroll
    for (int i = 0; i < 4; i++)
        g_gh[(tb + 16 * i) * H3 + j] = acc2[i] + b_hh[j];
}

// ---------------- K5: GRU gates + output --------------------------------------
__global__ void k5_gru(const float* __restrict__ states, float* __restrict__ out) {
    const int b = blockIdx.x, h = threadIdx.x;
    const float ir = g_gi[b * H3 + h],            hr = g_gh[b * H3 + h];
    const float iz = g_gi[b * H3 + HH + h],       hz = g_gh[b * H3 + HH + h];
    const float in_ = g_gi[b * H3 + 2 * HH + h],  hn = g_gh[b * H3 + 2 * HH + h];
    const float r = 1.f / (1.f + expf(-(ir + hr)));
    const float z = 1.f / (1.f + expf(-(iz + hz)));
    const float n = tanhf(in_ + r * hn);
    out[b * HH + h] = (1.f - z) * n + z * states[b * HH + h];
}

// ---------------- launch ------------------------------------------------------
extern "C" void kernel_launch(void* const* d_in, const int* in_sizes, int n_in,
                              void* d_out, int out_size) {
    const float* encoded = (const float*)d_in[0];
    const float* inputs  = (const float*)d_in[1];
    const float* states  = (const float*)d_in[2];
    const float* We      = (const float*)d_in[3];
    const float* be      = (const float*)d_in[4];
    const float* Wd      = (const float*)d_in[5];
    const float* bd      = (const float*)d_in[6];
    const float* Wv      = (const float*)d_in[7];
    const float* bv      = (const float*)d_in[8];
    const float* W_ih    = (const float*)d_in[9];
    const float* W_hh    = (const float*)d_in[10];
    const float* b_ih    = (const float*)d_in[11];
    const float* b_hh    = (const float*)d_in[12];
    float* out = (float*)d_out;

    cudaFuncSetAttribute(k2_scores, cudaFuncAttributeMaxDynamicSharedMemorySize,
                         K2_SMEMB);

    k0_convW<<<32, 256>>>(We);
    k1_decproj<<<BB, 128>>>(states, Wd, bd, be);
    k2_scores<<<dim3(SS / 128, BB), 256, K2_SMEMB>>>(encoded, Wv, bv);
    k3a_softmax<<<BB, 256>>>();
    k3b_att<<<dim3(HH / 128, SS / 256, BB), 256>>>(encoded);
    k4_gemm<<<H3 / 16, 256>>>(inputs, states, W_ih, W_hh, b_ih, b_hh);
    k5_gru<<<BB, 512>>>(states, out);
}

// round 6
// speedup vs baseline: 3.7826x; 1.1162x over previous
#include <cuda_runtime.h>
#include <cuda_bf16.h>
#include <math.h>
#include <cstdint>

// Problem dims (fixed by the dataset)
#define BB 64
#define SS 1024
#define HH 512
#define AA 128
#define DD 256
#define H3 1536   // 3*HH

// ---------------- scratch (no allocations allowed -> device globals) ----------
__device__ float g_dec[BB * AA];
__device__ float g_scores[BB * SS];
__device__ float g_probs[BB * SS];
__device__ float g_att[BB * HH];
__device__ float g_gi[BB * H3];
__device__ float g_gh[BB * H3];
__device__ __align__(16) uint32_t g_We_bf[AA * HH / 2];        // We bf16 [a][k]
__device__ __align__(16) uint32_t g_enc_bf[BB * SS * HH / 2];  // enc bf16 [b][s][k]

__device__ __forceinline__ float fast_tanh(float x) {
    float r;
    asm("tanh.approx.f32 %0, %1;" : "=f"(r) : "f"(x));
    return r;
}
__device__ __forceinline__ uint32_t smem_u32(const void* p) {
    uint32_t a;
    asm("{ .reg .u64 t; cvta.to.shared.u64 t, %1; cvt.u32.u64 %0, t; }"
        : "=r"(a) : "l"(p));
    return a;
}
__device__ __forceinline__ uint32_t pack_bf(float x, float y) {
    uint32_t r;
    asm("cvt.rn.bf16x2.f32 %0, %1, %2;" : "=r"(r) : "f"(y), "f"(x));
    return r;
}
__device__ __forceinline__ float bf_lo(uint32_t u) {
    return __uint_as_float(u << 16);
}
__device__ __forceinline__ float bf_hi(uint32_t u) {
    return __uint_as_float(u & 0xFFFF0000u);
}

// ---------------- K0a: convert We to bf16 once --------------------------------
__global__ void k0_convW(const float* __restrict__ We) {
    const int base = (blockIdx.x * 256 + threadIdx.x) * 4;
    const float2* W2 = (const float2*)We;
    #pragma unroll
    for (int i = 0; i < 4; i++) {
        float2 v = W2[base + i];
        g_We_bf[base + i] = pack_bf(v.x, v.y);
    }
}

// ---------------- K2a: convert encoded to bf16 (streaming) --------------------
__global__ __launch_bounds__(256) void k2a_conv(const float* __restrict__ enc) {
    const int g = blockIdx.x * 256 + threadIdx.x;   // 2.1M threads, 8 floats each
    const float4* e4 = (const float4*)enc;
    float4 v0 = e4[2 * g];
    float4 v1 = e4[2 * g + 1];
    uint4 o;
    o.x = pack_bf(v0.x, v0.y);
    o.y = pack_bf(v0.z, v0.w);
    o.z = pack_bf(v1.x, v1.y);
    o.w = pack_bf(v1.z, v1.w);
    ((uint4*)g_enc_bf)[g] = o;
}

// ---------------- K0c: init gate accumulators with biases ---------------------
__global__ void k0_init_gates(const float* __restrict__ b_ih,
                              const float* __restrict__ b_hh) {
    const int b = blockIdx.x;
    for (int j = threadIdx.x; j < H3; j += blockDim.x) {
        g_gi[b * H3 + j] = b_ih[j];
        g_gh[b * H3 + j] = b_hh[j];
    }
}

// ---------------- K1: dec_proj[b,a] = states[b]·Wd[a] + bd[a] + be[a] ---------
__global__ void k1_decproj(const float* __restrict__ states,
                           const float* __restrict__ Wd,
                           const float* __restrict__ bd,
                           const float* __restrict__ be) {
    int b = blockIdx.x;
    __shared__ float st[HH];
    for (int i = threadIdx.x; i < HH; i += blockDim.x) st[i] = states[b * HH + i];
    __syncthreads();
    int warp = threadIdx.x >> 5, lane = threadIdx.x & 31;
    for (int a = warp; a < AA; a += 4) {
        const float* w = Wd + a * HH;
        float sum = 0.f;
        for (int h = lane; h < HH; h += 32) sum += st[h] * w[h];
        #pragma unroll
        for (int o = 16; o; o >>= 1) sum += __shfl_xor_sync(0xffffffffu, sum, o);
        if (lane == 0) g_dec[b * AA + a] = sum + bd[a] + be[a];
    }
}

// ======= K2b: pure bf16 mma.sync GEMM (cp.async both operands) ================
// Block: 128 s x 128 a, K=512 in 8 chunks of 64 bf16 (128 B/row, SW128).
// 8 warps: warp_s=wid&3 (32 rows), warp_a=wid>>2 (64 cols).
#define K2_TILEB 16384
#define K2_W_OFF 32768
#define K2_SMEMB (4 * K2_TILEB + 2048)

__device__ __forceinline__ void cp16(uint32_t daddr, const void* src) {
    asm volatile("cp.async.cg.shared.global [%0], [%1], 16;" :: "r"(daddr), "l"(src));
}
__device__ __forceinline__ void cp_commit() {
    asm volatile("cp.async.commit_group;" ::: "memory");
}
__device__ __forceinline__ void ldsm4(uint32_t* r, uint32_t addr) {
    asm volatile("ldmatrix.sync.aligned.m8n8.x4.shared.b16 {%0,%1,%2,%3}, [%4];"
                 : "=r"(r[0]), "=r"(r[1]), "=r"(r[2]), "=r"(r[3]) : "r"(addr));
}
__device__ __forceinline__ void mma_bf16(float* d, const uint32_t* a,
                                         uint32_t b0, uint32_t b1) {
    asm volatile(
        "mma.sync.aligned.m16n8k16.row.col.f32.bf16.bf16.f32 "
        "{%0,%1,%2,%3}, {%4,%5,%6,%7}, {%8,%9}, {%0,%1,%2,%3};"
        : "+f"(d[0]), "+f"(d[1]), "+f"(d[2]), "+f"(d[3])
        : "r"(a[0]), "r"(a[1]), "r"(a[2]), "r"(a[3]), "r"(b0), "r"(b1));
}

__global__ __launch_bounds__(256, 2) void k2b_scores(const float* __restrict__ Wv,
                                                     const float* __restrict__ bv) {
    extern __shared__ float sm[];
    const uint32_t smem_base = smem_u32(sm);
    float* sdec = sm + 16384;   // byte 65536
    float* swv  = sm + 16512;
    float* sp   = sm + 16640;   // 2*128 floats

    const int b  = blockIdx.y;
    const int s0 = blockIdx.x * 128;
    const int tid = threadIdx.x;
    const int lane = tid & 31;
    const int wid = tid >> 5;
    const int warp_s = wid & 3;
    const int warp_a = wid >> 2;
    const int ms = warp_s * 32;
    const int na = warp_a * 64;

    if (tid < 128) {
        sdec[tid] = g_dec[b * AA + tid];
        swv[tid]  = Wv[tid];
    }

    const char* encb = (const char*)g_enc_bf + ((size_t)b * SS + s0) * 1024;
    const char* web  = (const char*)g_We_bf;
    const int r_st  = tid >> 3;   // 0..31 (+32i)
    const int sg_st = tid & 7;    // 16B segment 0..7

    float acc[2][8][4];
    #pragma unroll
    for (int f = 0; f < 2; f++)
        #pragma unroll
        for (int g = 0; g < 8; g++)
            #pragma unroll
            for (int q = 0; q < 4; q++) acc[f][g][q] = 0.f;

    // one cp.async group per chunk: E(16KB) + W(16KB), 8 segs/thread
    auto issue = [&](int c) {
        const int buf = c & 1;
        #pragma unroll
        for (int i = 0; i < 4; i++) {
            const int r = r_st + i * 32;
            const uint32_t sw = (uint32_t)(r * 128 + ((sg_st ^ (r & 7)) << 4));
            cp16(smem_base + buf * K2_TILEB + sw,
                 encb + (size_t)r * 1024 + c * 128 + sg_st * 16);
            cp16(smem_base + K2_W_OFF + buf * K2_TILEB + sw,
                 web + (size_t)r * 1024 + c * 128 + sg_st * 16);
        }
        cp_commit();
    };

    issue(0); issue(1);

    #pragma unroll
    for (int c = 0; c < 8; c++) {
        if (c < 7) asm volatile("cp.async.wait_group 1;" ::: "memory");
        else       asm volatile("cp.async.wait_group 0;" ::: "memory");
        __syncthreads();

        const uint32_t Eb = smem_base + (c & 1) * K2_TILEB;
        const uint32_t Wb = smem_base + K2_W_OFF + (c & 1) * K2_TILEB;
        #pragma unroll
        for (int ks = 0; ks < 4; ks++) {
            uint32_t afr[2][4];
            #pragma unroll
            for (int f = 0; f < 2; f++) {
                const int row = ms + f * 16 + (lane & 15);
                const int seg = ks * 2 + (lane >> 4);
                ldsm4(afr[f], Eb + row * 128 + ((seg ^ (row & 7)) << 4));
            }
            #pragma unroll
            for (int g2 = 0; g2 < 4; g2++) {
                const int row = na + g2 * 16 + ((lane >> 4) << 3) + (lane & 7);
                const int seg = ks * 2 + ((lane >> 3) & 1);
                uint32_t bfr[4];
                ldsm4(bfr, Wb + row * 128 + ((seg ^ (row & 7)) << 4));
                mma_bf16(acc[0][2 * g2],     afr[0], bfr[0], bfr[1]);
                mma_bf16(acc[0][2 * g2 + 1], afr[0], bfr[2], bfr[3]);
                mma_bf16(acc[1][2 * g2],     afr[1], bfr[0], bfr[1]);
                mma_bf16(acc[1][2 * g2 + 1], afr[1], bfr[2], bfr[3]);
            }
        }
        __syncthreads();
        if (c < 6) issue(c + 2);
    }

    // epilogue: tanh(acc + dec) * wv, reduce over a
    #pragma unroll
    for (int f = 0; f < 2; f++) {
        float pl = 0.f, ph = 0.f;
        #pragma unroll
        for (int g = 0; g < 8; g++) {
            const int a0 = warp_a * 64 + g * 8 + (lane & 3) * 2;
            const float d0 = sdec[a0], d1 = sdec[a0 + 1];
            const float w0 = swv[a0],  w1 = swv[a0 + 1];
            pl += fast_tanh(acc[f][g][0] + d0) * w0 + fast_tanh(acc[f][g][1] + d1) * w1;
            ph += fast_tanh(acc[f][g][2] + d0) * w0 + fast_tanh(acc[f][g][3] + d1) * w1;
        }
        pl += __shfl_xor_sync(0xffffffffu, pl, 1);
        pl += __shfl_xor_sync(0xffffffffu, pl, 2);
        ph += __shfl_xor_sync(0xffffffffu, ph, 1);
        ph += __shfl_xor_sync(0xffffffffu, ph, 2);
        if ((lane & 3) == 0) {
            const int sl = ms + f * 16 + (lane >> 2);
            sp[warp_a * 128 + sl]     = pl;
            sp[warp_a * 128 + sl + 8] = ph;
        }
    }
    __syncthreads();
    if (tid < 128)
        g_scores[b * SS + s0 + tid] = sp[tid] + sp[128 + tid] + bv[0];
}

// ---------------- K3a: softmax over seq per batch (+ zero g_att) --------------
__global__ void k3a_softmax() {
    const int b = blockIdx.x, tid = threadIdx.x;
    for (int i = tid; i < HH; i += 256) g_att[b * HH + i] = 0.f;

    __shared__ float red[256];
    float v[4];
    float mx = -1e30f;
    #pragma unroll
    for (int r = 0; r < 4; r++) {
        v[r] = g_scores[b * SS + tid + 256 * r];
        mx = fmaxf(mx, v[r]);
    }
    red[tid] = mx;
    __syncthreads();
    for (int o = 128; o; o >>= 1) {
        if (tid < o) red[tid] = fmaxf(red[tid], red[tid + o]);
        __syncthreads();
    }
    mx = red[0];
    __syncthreads();
    float sum = 0.f;
    #pragma unroll
    for (int r = 0; r < 4; r++) { v[r] = expf(v[r] - mx); sum += v[r]; }
    red[tid] = sum;
    __syncthreads();
    for (int o = 128; o; o >>= 1) {
        if (tid < o) red[tid] += red[tid + o];
        __syncthreads();
    }
    const float inv = 1.f / red[0];
    #pragma unroll
    for (int r = 0; r < 4; r++) g_probs[b * SS + tid + 256 * r] = v[r] * inv;
}

// ---------------- K3b: attention from bf16 enc (half the traffic) -------------
// grid (HH/128=4, SS/256=4, BB), 256 threads; each thread: 4 h via uint2 loads.
__global__ __launch_bounds__(256) void k3b_att() {
    const int b  = blockIdx.z;
    const int sb = blockIdx.y;
    const int hb = blockIdx.x;
    const int lane = threadIdx.x & 31;
    const int srow = threadIdx.x >> 5;
    // uint2 index: row*128 + hb*32 + lane  (row stride = 512 bf16 = 128 uint2)
    const uint2* e = (const uint2*)g_enc_bf
                   + ((size_t)b * SS + sb * 256 + srow) * 128 + hb * 32 + lane;
    const float* pr = g_probs + b * SS + sb * 256 + srow;

    float4 a0 = {0.f, 0.f, 0.f, 0.f}, a1 = {0.f, 0.f, 0.f, 0.f};
    #pragma unroll 4
    for (int i = 0; i < 32; i += 2) {
        const float p0 = pr[i * 8];
        const float p1 = pr[(i + 1) * 8];
        const uint2 u0 = e[(size_t)i * 8 * 128];
        const uint2 u1 = e[(size_t)(i + 1) * 8 * 128];
        a0.x = fmaf(p0, bf_lo(u0.x), a0.x); a0.y = fmaf(p0, bf_hi(u0.x), a0.y);
        a0.z = fmaf(p0, bf_lo(u0.y), a0.z); a0.w = fmaf(p0, bf_hi(u0.y), a0.w);
        a1.x = fmaf(p1, bf_lo(u1.x), a1.x); a1.y = fmaf(p1, bf_hi(u1.x), a1.y);
        a1.z = fmaf(p1, bf_lo(u1.y), a1.z); a1.w = fmaf(p1, bf_hi(u1.y), a1.w);
    }
    a0.x += a1.x; a0.y += a1.y; a0.z += a1.z; a0.w += a1.w;

    __shared__ float red[8][32][4];
    red[srow][lane][0] = a0.x;
    red[srow][lane][1] = a0.y;
    red[srow][lane][2] = a0.z;
    red[srow][lane][3] = a0.w;
    __syncthreads();
    if (threadIdx.x < 128) {
        const int l = threadIdx.x & 31;
        const int comp = threadIdx.x >> 5;
        float s = 0.f;
        #pragma unroll
        for (int r = 0; r < 8; r++) s += red[r][l][comp];
        atomicAdd(&g_att[b * HH + hb * 128 + l * 4 + comp], s);
    }
}

// ---------------- K4: gate GEMMs, phase x K-half split, atomic accumulate -----
// grid (96, 4): y>>1 = phase (0: gi, 1: gh), y&1 = K-half.
__global__ __launch_bounds__(256) void k4_gemm(const float* __restrict__ inputs,
                                               const float* __restrict__ states,
                                               const float* __restrict__ W_ih,
                                               const float* __restrict__ W_hh) {
    const int j0 = blockIdx.x * 16;
    const int phase = blockIdx.y >> 1;
    const int half  = blockIdx.y & 1;
    const int tid = threadIdx.x;
    const int tx = tid & 15;
    const int tb = tid >> 4;
    const int j = j0 + tx;
    __shared__ float Xs[64][65];
    __shared__ float Wsm[64][17];

    float acc[4] = {0.f, 0.f, 0.f, 0.f};
    if (phase == 0) {
        const int kbeg = half * 384, kend = kbeg + 384;
        for (int k0 = kbeg; k0 < kend; k0 += 64) {
            #pragma unroll
            for (int it = 0; it < 16; it++) {
                int idx = it * 256 + tid;
                int bb = idx >> 6, k = idx & 63;
                int kg = k0 + k;
                Xs[k][bb] = (kg < DD) ? inputs[bb * DD + kg]
                                      : g_att[bb * HH + (kg - DD)];
            }
            #pragma unroll
            for (int it = 0; it < 4; it++) {
                int idx = it * 256 + tid;
                int jj = idx >> 6, k = idx & 63;
                Wsm[k][jj] = W_ih[(j0 + jj) * (DD + HH) + k0 + k];
            }
            __syncthreads();
            #pragma unroll
            for (int k = 0; k < 64; k++) {
                float w = Wsm[k][tx];
                #pragma unroll
                for (int i = 0; i < 4; i++)
                    acc[i] = fmaf(Xs[k][tb + 16 * i], w, acc[i]);
            }
            __syncthreads();
        }
        #pragma unroll
        for (int i = 0; i < 4; i++)
            atomicAdd(&g_gi[(tb + 16 * i) * H3 + j], acc[i]);
    } else {
        const int kbeg = half * 256, kend = kbeg + 256;
        for (int k0 = kbeg; k0 < kend; k0 += 64) {
            #pragma unroll
            for (int it = 0; it < 16; it++) {
                int idx = it * 256 + tid;
                int bb = idx >> 6, k = idx & 63;
                Xs[k][bb] = states[bb * HH + k0 + k];
            }
            #pragma unroll
            for (int it = 0; it < 4; it++) {
                int idx = it * 256 + tid;
                int jj = idx >> 6, k = idx & 63;
                Wsm[k][jj] = W_hh[(j0 + jj) * HH + k0 + k];
            }
            __syncthreads();
            #pragma unroll
            for (int k = 0; k < 64; k++) {
                float w = Wsm[k][tx];
                #pragma unroll
                for (int i = 0; i < 4; i++)
                    acc[i] = fmaf(Xs[k][tb + 16 * i], w, acc[i]);
            }
            __syncthreads();
        }
        #pragma unroll
        for (int i = 0; i < 4; i++)
            atomicAdd(&g_gh[(tb + 16 * i) * H3 + j], acc[i]);
    }
}

// ---------------- K5: GRU gates + output --------------------------------------
__global__ void k5_gru(const float* __restrict__ states, float* __restrict__ out) {
    const int b = blockIdx.x, h = threadIdx.x;
    const float ir = g_gi[b * H3 + h],            hr = g_gh[b * H3 + h];
    const float iz = g_gi[b * H3 + HH + h],       hz = g_gh[b * H3 + HH + h];
    const float in_ = g_gi[b * H3 + 2 * HH + h],  hn = g_gh[b * H3 + 2 * HH + h];
    const float r = 1.f / (1.f + expf(-(ir + hr)));
    const float z = 1.f / (1.f + expf(-(iz + hz)));
    const float n = tanhf(in_ + r * hn);
    out[b * HH + h] = (1.f - z) * n + z * states[b * HH + h];
}

// ---------------- launch ------------------------------------------------------
extern "C" void kernel_launch(void* const* d_in, const int* in_sizes, int n_in,
                              void* d_out, int out_size) {
    const float* encoded = (const float*)d_in[0];
    const float* inputs  = (const float*)d_in[1];
    const float* states  = (const float*)d_in[2];
    const float* We      = (const float*)d_in[3];
    const float* be      = (const float*)d_in[4];
    const float* Wd      = (const float*)d_in[5];
    const float* bd      = (const float*)d_in[6];
    const float* Wv      = (const float*)d_in[7];
    const float* bv      = (const float*)d_in[8];
    const float* W_ih    = (const float*)d_in[9];
    const float* W_hh    = (const float*)d_in[10];
    const float* b_ih    = (const float*)d_in[11];
    const float* b_hh    = (const float*)d_in[12];
    float* out = (float*)d_out;

    cudaFuncSetAttribute(k2b_scores, cudaFuncAttributeMaxDynamicSharedMemorySize,
                         K2_SMEMB);

    k0_convW<<<32, 256>>>(We);
    k2a_conv<<<BB * SS * HH / (256 * 8), 256>>>(encoded);
    k0_init_gates<<<BB, 512>>>(b_ih, b_hh);
    k1_decproj<<<BB, 128>>>(states, Wd, bd, be);
    k2b_scores<<<dim3(SS / 128, BB), 256, K2_SMEMB>>>(Wv, bv);
    k3a_softmax<<<BB, 256>>>();
    k3b_att<<<dim3(HH / 128, SS / 256, BB), 256>>>();
    k4_gemm<<<dim3(H3 / 16, 4), 256>>>(inputs, states, W_ih, W_hh);
    k5_gru<<<BB, 512>>>(states, out);
}

// round 7
// speedup vs baseline: 4.8333x; 1.2778x over previous
#include <cuda_runtime.h>
#include <cuda_bf16.h>
#include <math.h>
#include <cstdint>

// Problem dims (fixed by the dataset)
#define BB 64
#define SS 1024
#define HH 512
#define AA 128
#define DD 256
#define H3 1536   // 3*HH

// ---------------- scratch (no allocations allowed -> device globals) ----------
__device__ float g_dec[BB * AA];
__device__ float g_scores[BB * SS];
__device__ float g_probs[BB * SS];
__device__ float g_att[BB * HH];
__device__ float g_p0[BB * H3];   // gi partial (K-half 0)
__device__ float g_p1[BB * H3];   // gi partial (K-half 1)
__device__ float g_q0[BB * H3];   // gh partial (K-half 0)
__device__ float g_q1[BB * H3];   // gh partial (K-half 1)
__device__ __align__(16) uint32_t g_We_bf[AA * HH / 2];        // We bf16 [a][k]
__device__ __align__(16) uint32_t g_enc_bf[BB * SS * HH / 2];  // enc bf16 [b][s][k]

__device__ __forceinline__ float fast_tanh(float x) {
    float r;
    asm("tanh.approx.f32 %0, %1;" : "=f"(r) : "f"(x));
    return r;
}
__device__ __forceinline__ uint32_t smem_u32(const void* p) {
    uint32_t a;
    asm("{ .reg .u64 t; cvta.to.shared.u64 t, %1; cvt.u32.u64 %0, t; }"
        : "=r"(a) : "l"(p));
    return a;
}
__device__ __forceinline__ uint32_t pack_bf(float x, float y) {
    uint32_t r;
    asm("cvt.rn.bf16x2.f32 %0, %1, %2;" : "=r"(r) : "f"(y), "f"(x));
    return r;
}
__device__ __forceinline__ float bf_lo(uint32_t u) {
    return __uint_as_float(u << 16);
}
__device__ __forceinline__ float bf_hi(uint32_t u) {
    return __uint_as_float(u & 0xFFFF0000u);
}

// ---------------- K0a: convert We to bf16 once --------------------------------
__global__ void k0_convW(const float* __restrict__ We) {
    const int base = (blockIdx.x * 256 + threadIdx.x) * 4;
    const float2* W2 = (const float2*)We;
    #pragma unroll
    for (int i = 0; i < 4; i++) {
        float2 v = W2[base + i];
        g_We_bf[base + i] = pack_bf(v.x, v.y);
    }
}

// ---------------- K2a: convert encoded to bf16 (streaming) --------------------
__global__ __launch_bounds__(256) void k2a_conv(const float* __restrict__ enc) {
    const int g = blockIdx.x * 256 + threadIdx.x;   // 2.1M threads, 8 floats each
    const float4* e4 = (const float4*)enc;
    float4 v0 = e4[2 * g];
    float4 v1 = e4[2 * g + 1];
    uint4 o;
    o.x = pack_bf(v0.x, v0.y);
    o.y = pack_bf(v0.z, v0.w);
    o.z = pack_bf(v1.x, v1.y);
    o.w = pack_bf(v1.z, v1.w);
    ((uint4*)g_enc_bf)[g] = o;
}

// ---------------- K1: dec_proj[b,a] = states[b]·Wd[a] + bd[a] + be[a] ---------
// grid (BB, 8), 128 threads: warp w handles a = by*16 + w*4 + i, float4 loads.
__global__ __launch_bounds__(128) void k1_decproj(const float* __restrict__ states,
                                                  const float* __restrict__ Wd,
                                                  const float* __restrict__ bd,
                                                  const float* __restrict__ be) {
    const int b = blockIdx.x;
    const int a0 = blockIdx.y * 16 + (threadIdx.x >> 5) * 4;
    const int lane = threadIdx.x & 31;

    const float4* st4 = (const float4*)(states + b * HH);
    float4 st[4];
    #pragma unroll
    for (int j = 0; j < 4; j++) st[j] = st4[lane + 32 * j];

    #pragma unroll
    for (int i = 0; i < 4; i++) {
        const int a = a0 + i;
        const float4* w4 = (const float4*)(Wd + (size_t)a * HH);
        float s = 0.f;
        #pragma unroll
        for (int j = 0; j < 4; j++) {
            const float4 w = w4[lane + 32 * j];
            s += st[j].x * w.x + st[j].y * w.y + st[j].z * w.z + st[j].w * w.w;
        }
        #pragma unroll
        for (int o = 16; o; o >>= 1) s += __shfl_xor_sync(0xffffffffu, s, o);
        if (lane == 0) g_dec[b * AA + a] = s + bd[a] + be[a];
    }
}

// ======= K2b: pure bf16 mma.sync GEMM (cp.async both operands) ================
// Block: 128 s x 128 a, K=512 in 8 chunks of 64 bf16 (128 B/row, SW128).
// 8 warps: warp_s=wid&3 (32 rows), warp_a=wid>>2 (64 cols).
#define K2_TILEB 16384
#define K2_W_OFF 32768
#define K2_SMEMB (4 * K2_TILEB + 2048)

__device__ __forceinline__ void cp16(uint32_t daddr, const void* src) {
    asm volatile("cp.async.cg.shared.global [%0], [%1], 16;" :: "r"(daddr), "l"(src));
}
__device__ __forceinline__ void cp_commit() {
    asm volatile("cp.async.commit_group;" ::: "memory");
}
__device__ __forceinline__ void ldsm4(uint32_t* r, uint32_t addr) {
    asm volatile("ldmatrix.sync.aligned.m8n8.x4.shared.b16 {%0,%1,%2,%3}, [%4];"
                 : "=r"(r[0]), "=r"(r[1]), "=r"(r[2]), "=r"(r[3]) : "r"(addr));
}
__device__ __forceinline__ void mma_bf16(float* d, const uint32_t* a,
                                         uint32_t b0, uint32_t b1) {
    asm volatile(
        "mma.sync.aligned.m16n8k16.row.col.f32.bf16.bf16.f32 "
        "{%0,%1,%2,%3}, {%4,%5,%6,%7}, {%8,%9}, {%0,%1,%2,%3};"
        : "+f"(d[0]), "+f"(d[1]), "+f"(d[2]), "+f"(d[3])
        : "r"(a[0]), "r"(a[1]), "r"(a[2]), "r"(a[3]), "r"(b0), "r"(b1));
}

__global__ __launch_bounds__(256, 2) void k2b_scores(const float* __restrict__ Wv,
                                                     const float* __restrict__ bv) {
    extern __shared__ float sm[];
    const uint32_t smem_base = smem_u32(sm);
    float* sdec = sm + 16384;   // byte 65536
    float* swv  = sm + 16512;
    float* sp   = sm + 16640;   // 2*128 floats

    const int b  = blockIdx.y;
    const int s0 = blockIdx.x * 128;
    const int tid = threadIdx.x;
    const int lane = tid & 31;
    const int wid = tid >> 5;
    const int warp_s = wid & 3;
    const int warp_a = wid >> 2;
    const int ms = warp_s * 32;
    const int na = warp_a * 64;

    if (tid < 128) {
        sdec[tid] = g_dec[b * AA + tid];
        swv[tid]  = Wv[tid];
    }

    const char* encb = (const char*)g_enc_bf + ((size_t)b * SS + s0) * 1024;
    const char* web  = (const char*)g_We_bf;
    const int r_st  = tid >> 3;   // 0..31 (+32i)
    const int sg_st = tid & 7;    // 16B segment 0..7

    float acc[2][8][4];
    #pragma unroll
    for (int f = 0; f < 2; f++)
        #pragma unroll
        for (int g = 0; g < 8; g++)
            #pragma unroll
            for (int q = 0; q < 4; q++) acc[f][g][q] = 0.f;

    // one cp.async group per chunk: E(16KB) + W(16KB), 8 segs/thread
    auto issue = [&](int c) {
        const int buf = c & 1;
        #pragma unroll
        for (int i = 0; i < 4; i++) {
            const int r = r_st + i * 32;
            const uint32_t sw = (uint32_t)(r * 128 + ((sg_st ^ (r & 7)) << 4));
            cp16(smem_base + buf * K2_TILEB + sw,
                 encb + (size_t)r * 1024 + c * 128 + sg_st * 16);
            cp16(smem_base + K2_W_OFF + buf * K2_TILEB + sw,
                 web + (size_t)r * 1024 + c * 128 + sg_st * 16);
        }
        cp_commit();
    };

    issue(0); issue(1);

    #pragma unroll
    for (int c = 0; c < 8; c++) {
        if (c < 7) asm volatile("cp.async.wait_group 1;" ::: "memory");
        else       asm volatile("cp.async.wait_group 0;" ::: "memory");
        __syncthreads();

        const uint32_t Eb = smem_base + (c & 1) * K2_TILEB;
        const uint32_t Wb = smem_base + K2_W_OFF + (c & 1) * K2_TILEB;
        #pragma unroll
        for (int ks = 0; ks < 4; ks++) {
            uint32_t afr[2][4];
            #pragma unroll
            for (int f = 0; f < 2; f++) {
                const int row = ms + f * 16 + (lane & 15);
                const int seg = ks * 2 + (lane >> 4);
                ldsm4(afr[f], Eb + row * 128 + ((seg ^ (row & 7)) << 4));
            }
            #pragma unroll
            for (int g2 = 0; g2 < 4; g2++) {
                const int row = na + g2 * 16 + ((lane >> 4) << 3) + (lane & 7);
                const int seg = ks * 2 + ((lane >> 3) & 1);
                uint32_t bfr[4];
                ldsm4(bfr, Wb + row * 128 + ((seg ^ (row & 7)) << 4));
                mma_bf16(acc[0][2 * g2],     afr[0], bfr[0], bfr[1]);
                mma_bf16(acc[0][2 * g2 + 1], afr[0], bfr[2], bfr[3]);
                mma_bf16(acc[1][2 * g2],     afr[1], bfr[0], bfr[1]);
                mma_bf16(acc[1][2 * g2 + 1], afr[1], bfr[2], bfr[3]);
            }
        }
        __syncthreads();
        if (c < 6) issue(c + 2);
    }

    // epilogue: tanh(acc + dec) * wv, reduce over a
    #pragma unroll
    for (int f = 0; f < 2; f++) {
        float pl = 0.f, ph = 0.f;
        #pragma unroll
        for (int g = 0; g < 8; g++) {
            const int a0 = warp_a * 64 + g * 8 + (lane & 3) * 2;
            const float d0 = sdec[a0], d1 = sdec[a0 + 1];
            const float w0 = swv[a0],  w1 = swv[a0 + 1];
            pl += fast_tanh(acc[f][g][0] + d0) * w0 + fast_tanh(acc[f][g][1] + d1) * w1;
            ph += fast_tanh(acc[f][g][2] + d0) * w0 + fast_tanh(acc[f][g][3] + d1) * w1;
        }
        pl += __shfl_xor_sync(0xffffffffu, pl, 1);
        pl += __shfl_xor_sync(0xffffffffu, pl, 2);
        ph += __shfl_xor_sync(0xffffffffu, ph, 1);
        ph += __shfl_xor_sync(0xffffffffu, ph, 2);
        if ((lane & 3) == 0) {
            const int sl = ms + f * 16 + (lane >> 2);
            sp[warp_a * 128 + sl]     = pl;
            sp[warp_a * 128 + sl + 8] = ph;
        }
    }
    __syncthreads();
    if (tid < 128)
        g_scores[b * SS + s0 + tid] = sp[tid] + sp[128 + tid] + bv[0];
}

// ---------------- K3a: softmax over seq per batch (+ zero g_att) --------------
// grid BB, block 1024: one element per thread, shuffle reductions.
__global__ __launch_bounds__(1024) void k3a_softmax() {
    const int b = blockIdx.x, tid = threadIdx.x;
    const int lane = tid & 31, warp = tid >> 5;
    __shared__ float red[32];
    __shared__ float bcast;

    if (tid < HH) g_att[b * HH + tid] = 0.f;

    float v = g_scores[b * SS + tid];

    // --- max ---
    float m = v;
    #pragma unroll
    for (int o = 16; o; o >>= 1) m = fmaxf(m, __shfl_xor_sync(0xffffffffu, m, o));
    if (lane == 0) red[warp] = m;
    __syncthreads();
    if (warp == 0) {
        float t = red[lane];
        #pragma unroll
        for (int o = 16; o; o >>= 1) t = fmaxf(t, __shfl_xor_sync(0xffffffffu, t, o));
        if (lane == 0) bcast = t;
    }
    __syncthreads();
    const float mx = bcast;

    // --- sum ---
    const float e = expf(v - mx);
    float s = e;
    #pragma unroll
    for (int o = 16; o; o >>= 1) s += __shfl_xor_sync(0xffffffffu, s, o);
    __syncthreads();
    if (lane == 0) red[warp] = s;
    __syncthreads();
    if (warp == 0) {
        float t = red[lane];
        #pragma unroll
        for (int o = 16; o; o >>= 1) t += __shfl_xor_sync(0xffffffffu, t, o);
        if (lane == 0) bcast = 1.f / t;
    }
    __syncthreads();
    g_probs[b * SS + tid] = e * bcast;
}

// ---------------- K3b: attention from bf16 enc (half the traffic) -------------
// grid (HH/128=4, SS/256=4, BB), 256 threads; each thread: 4 h via uint2 loads.
__global__ __launch_bounds__(256) void k3b_att() {
    const int b  = blockIdx.z;
    const int sb = blockIdx.y;
    const int hb = blockIdx.x;
    const int lane = threadIdx.x & 31;
    const int srow = threadIdx.x >> 5;
    const uint2* e = (const uint2*)g_enc_bf
                   + ((size_t)b * SS + sb * 256 + srow) * 128 + hb * 32 + lane;
    const float* pr = g_probs + b * SS + sb * 256 + srow;

    float4 a0 = {0.f, 0.f, 0.f, 0.f}, a1 = {0.f, 0.f, 0.f, 0.f};
    #pragma unroll 4
    for (int i = 0; i < 32; i += 2) {
        const float p0 = pr[i * 8];
        const float p1 = pr[(i + 1) * 8];
        const uint2 u0 = e[(size_t)i * 8 * 128];
        const uint2 u1 = e[(size_t)(i + 1) * 8 * 128];
        a0.x = fmaf(p0, bf_lo(u0.x), a0.x); a0.y = fmaf(p0, bf_hi(u0.x), a0.y);
        a0.z = fmaf(p0, bf_lo(u0.y), a0.z); a0.w = fmaf(p0, bf_hi(u0.y), a0.w);
        a1.x = fmaf(p1, bf_lo(u1.x), a1.x); a1.y = fmaf(p1, bf_hi(u1.x), a1.y);
        a1.z = fmaf(p1, bf_lo(u1.y), a1.z); a1.w = fmaf(p1, bf_hi(u1.y), a1.w);
    }
    a0.x += a1.x; a0.y += a1.y; a0.z += a1.z; a0.w += a1.w;

    __shared__ float red[8][32][4];
    red[srow][lane][0] = a0.x;
    red[srow][lane][1] = a0.y;
    red[srow][lane][2] = a0.z;
    red[srow][lane][3] = a0.w;
    __syncthreads();
    if (threadIdx.x < 128) {
        const int l = threadIdx.x & 31;
        const int comp = threadIdx.x >> 5;
        float s = 0.f;
        #pragma unroll
        for (int r = 0; r < 8; r++) s += red[r][l][comp];
        atomicAdd(&g_att[b * HH + hb * 128 + l * 4 + comp], s);
    }
}

// ---------------- K4: gate GEMMs, phase x K-half split, partial buffers -------
// grid (96, 4): y>>1 = phase (0: gi, 1: gh), y&1 = K-half. No atomics:
// each (phase, half) writes its own partial buffer; k5 sums them + biases.
__global__ __launch_bounds__(256) void k4_gemm(const float* __restrict__ inputs,
                                               const float* __restrict__ states,
                                               const float* __restrict__ W_ih,
                                               const float* __restrict__ W_hh) {
    const int j0 = blockIdx.x * 16;
    const int phase = blockIdx.y >> 1;
    const int half  = blockIdx.y & 1;
    const int tid = threadIdx.x;
    const int tx = tid & 15;
    const int tb = tid >> 4;
    const int j = j0 + tx;
    __shared__ float Xs[64][65];
    __shared__ float Wsm[64][17];

    float acc[4] = {0.f, 0.f, 0.f, 0.f};
    if (phase == 0) {
        const int kbeg = half * 384, kend = kbeg + 384;
        for (int k0 = kbeg; k0 < kend; k0 += 64) {
            #pragma unroll
            for (int it = 0; it < 16; it++) {
                int idx = it * 256 + tid;
                int bb = idx >> 6, k = idx & 63;
                int kg = k0 + k;
                Xs[k][bb] = (kg < DD) ? inputs[bb * DD + kg]
                                      : g_att[bb * HH + (kg - DD)];
            }
            #pragma unroll
            for (int it = 0; it < 4; it++) {
                int idx = it * 256 + tid;
                int jj = idx >> 6, k = idx & 63;
                Wsm[k][jj] = W_ih[(j0 + jj) * (DD + HH) + k0 + k];
            }
            __syncthreads();
            #pragma unroll
            for (int k = 0; k < 64; k++) {
                float w = Wsm[k][tx];
                #pragma unroll
                for (int i = 0; i < 4; i++)
                    acc[i] = fmaf(Xs[k][tb + 16 * i], w, acc[i]);
            }
            __syncthreads();
        }
        float* dst = half ? g_p1 : g_p0;
        #pragma unroll
        for (int i = 0; i < 4; i++)
            dst[(tb + 16 * i) * H3 + j] = acc[i];
    } else {
        const int kbeg = half * 256, kend = kbeg + 256;
        for (int k0 = kbeg; k0 < kend; k0 += 64) {
            #pragma unroll
            for (int it = 0; it < 16; it++) {
                int idx = it * 256 + tid;
                int bb = idx >> 6, k = idx & 63;
                Xs[k][bb] = states[bb * HH + k0 + k];
            }
            #pragma unroll
            for (int it = 0; it < 4; it++) {
                int idx = it * 256 + tid;
                int jj = idx >> 6, k = idx & 63;
                Wsm[k][jj] = W_hh[(j0 + jj) * HH + k0 + k];
            }
            __syncthreads();
            #pragma unroll
            for (int k = 0; k < 64; k++) {
                float w = Wsm[k][tx];
                #pragma unroll
                for (int i = 0; i < 4; i++)
                    acc[i] = fmaf(Xs[k][tb + 16 * i], w, acc[i]);
            }
            __syncthreads();
        }
        float* dst = half ? g_q1 : g_q0;
        #pragma unroll
        for (int i = 0; i < 4; i++)
            dst[(tb + 16 * i) * H3 + j] = acc[i];
    }
}

// ---------------- K5: GRU gates + output (sum partials + biases) --------------
__global__ void k5_gru(const float* __restrict__ states,
                       const float* __restrict__ b_ih,
                       const float* __restrict__ b_hh,
                       float* __restrict__ out) {
    const int b = blockIdx.x, h = threadIdx.x;
    const int o0 = b * H3 + h, o1 = o0 + HH, o2 = o1 + HH;
    const float ir = g_p0[o0] + g_p1[o0] + b_ih[h];
    const float iz = g_p0[o1] + g_p1[o1] + b_ih[HH + h];
    const float in_ = g_p0[o2] + g_p1[o2] + b_ih[2 * HH + h];
    const float hr = g_q0[o0] + g_q1[o0] + b_hh[h];
    const float hz = g_q0[o1] + g_q1[o1] + b_hh[HH + h];
    const float hn = g_q0[o2] + g_q1[o2] + b_hh[2 * HH + h];
    const float r = 1.f / (1.f + expf(-(ir + hr)));
    const float z = 1.f / (1.f + expf(-(iz + hz)));
    const float n = tanhf(in_ + r * hn);
    out[b * HH + h] = (1.f - z) * n + z * states[b * HH + h];
}

// ---------------- launch ------------------------------------------------------
extern "C" void kernel_launch(void* const* d_in, const int* in_sizes, int n_in,
                              void* d_out, int out_size) {
    const float* encoded = (const float*)d_in[0];
    const float* inputs  = (const float*)d_in[1];
    const float* states  = (const float*)d_in[2];
    const float* We      = (const float*)d_in[3];
    const float* be      = (const float*)d_in[4];
    const float* Wd      = (const float*)d_in[5];
    const float* bd      = (const float*)d_in[6];
    const float* Wv      = (const float*)d_in[7];
    const float* bv      = (const float*)d_in[8];
    const float* W_ih    = (const float*)d_in[9];
    const float* W_hh    = (const float*)d_in[10];
    const float* b_ih    = (const float*)d_in[11];
    const float* b_hh    = (const float*)d_in[12];
    float* out = (float*)d_out;

    cudaFuncSetAttribute(k2b_scores, cudaFuncAttributeMaxDynamicSharedMemorySize,
                         K2_SMEMB);

    k0_convW<<<32, 256>>>(We);
    k2a_conv<<<BB * SS * HH / (256 * 8), 256>>>(encoded);
    k1_decproj<<<dim3(BB, 8), 128>>>(states, Wd, bd, be);
    k2b_scores<<<dim3(SS / 128, BB), 256, K2_SMEMB>>>(Wv, bv);
    k3a_softmax<<<BB, 1024>>>();
    k3b_att<<<dim3(HH / 128, SS / 256, BB), 256>>>();
    k4_gemm<<<dim3(H3 / 16, 4), 256>>>(inputs, states, W_ih, W_hh);
    k5_gru<<<BB, 512>>>(states, b_ih, b_hh, out);
}

// round 10
// speedup vs baseline: 5.0192x; 1.0385x over previous
#include <cuda_runtime.h>
#include <cuda_bf16.h>
#include <math.h>
#include <cstdint>

// Problem dims (fixed by the dataset)
#define BB 64
#define SS 1024
#define HH 512
#define AA 128
#define DD 256
#define H3 1536   // 3*HH

// ---------------- scratch (no allocations allowed -> device globals) ----------
__device__ float g_dec[BB * AA];
__device__ float g_scores[BB * SS];
__device__ float g_probs[BB * SS];
__device__ float g_att[BB * HH];
__device__ float g_p0[BB * H3];   // gi partial (K-half 0)
__device__ float g_p1[BB * H3];   // gi partial (K-half 1)
__device__ float g_q0[BB * H3];   // gh partial (K-half 0)
__device__ float g_q1[BB * H3];   // gh partial (K-half 1)
__device__ __align__(32) uint32_t g_We_bf[AA * HH / 2];        // We bf16 [a][k]
__device__ __align__(32) uint32_t g_enc_bf[BB * SS * HH / 2];  // enc bf16 [b][s][k]

__device__ __forceinline__ float fast_tanh(float x) {
    float r;
    asm("tanh.approx.f32 %0, %1;" : "=f"(r) : "f"(x));
    return r;
}
__device__ __forceinline__ uint32_t smem_u32(const void* p) {
    uint32_t a;
    asm("{ .reg .u64 t; cvta.to.shared.u64 t, %1; cvt.u32.u64 %0, t; }"
        : "=r"(a) : "l"(p));
    return a;
}
__device__ __forceinline__ uint32_t pack_bf(float x, float y) {
    uint32_t r;
    asm("cvt.rn.bf16x2.f32 %0, %1, %2;" : "=r"(r) : "f"(y), "f"(x));
    return r;
}
__device__ __forceinline__ uint64_t pack_bf4(float x, float y, float z, float w) {
    const uint32_t lo = pack_bf(x, y);
    const uint32_t hi = pack_bf(z, w);
    return ((uint64_t)hi << 32) | lo;
}
__device__ __forceinline__ float bf_lo(uint32_t u) {
    return __uint_as_float(u << 16);
}
__device__ __forceinline__ float bf_hi(uint32_t u) {
    return __uint_as_float(u & 0xFFFF0000u);
}

// ---------------- K0a: convert We to bf16 once --------------------------------
__global__ void k0_convW(const float* __restrict__ We) {
    const int base = (blockIdx.x * 256 + threadIdx.x) * 4;
    const float2* W2 = (const float2*)We;
    #pragma unroll
    for (int i = 0; i < 4; i++) {
        float2 v = W2[base + i];
        g_We_bf[base + i] = pack_bf(v.x, v.y);
    }
}

// ---------------- K2a: convert encoded to bf16 (streaming, L2-pinned out) -----
// Each thread: 16 floats in (4x float4, streaming), 32 bytes out (v4.b64,
// evict_last -> bf16 copy stays L2-resident for k2b + k3b).
__global__ __launch_bounds__(256) void k2a_conv(const float* __restrict__ enc) {
    const int g = blockIdx.x * 256 + threadIdx.x;   // 1.05M threads
    const float4* e4 = (const float4*)enc;
    float4 v0 = __ldcs(e4 + 4 * g);
    float4 v1 = __ldcs(e4 + 4 * g + 1);
    float4 v2 = __ldcs(e4 + 4 * g + 2);
    float4 v3 = __ldcs(e4 + 4 * g + 3);
    uint64_t d0 = pack_bf4(v0.x, v0.y, v0.z, v0.w);
    uint64_t d1 = pack_bf4(v1.x, v1.y, v1.z, v1.w);
    uint64_t d2 = pack_bf4(v2.x, v2.y, v2.z, v2.w);
    uint64_t d3 = pack_bf4(v3.x, v3.y, v3.z, v3.w);
    asm volatile("st.global.L2::evict_last.v4.b64 [%0], {%1,%2,%3,%4};"
                 :: "l"((char*)g_enc_bf + (size_t)g * 32),
                    "l"(d0), "l"(d1), "l"(d2), "l"(d3)
                 : "memory");
}

// ---------------- K1: dec_proj[b,a] = states[b]·Wd[a] + bd[a] + be[a] ---------
// grid (BB, 8), 128 threads: warp w handles a = by*16 + w*4 + i, float4 loads.
__global__ __launch_bounds__(128) void k1_decproj(const float* __restrict__ states,
                                                  const float* __restrict__ Wd,
                                                  const float* __restrict__ bd,
                                                  const float* __restrict__ be) {
    const int b = blockIdx.x;
    const int a0 = blockIdx.y * 16 + (threadIdx.x >> 5) * 4;
    const int lane = threadIdx.x & 31;

    const float4* st4 = (const float4*)(states + b * HH);
    float4 st[4];
    #pragma unroll
    for (int j = 0; j < 4; j++) st[j] = st4[lane + 32 * j];

    #pragma unroll
    for (int i = 0; i < 4; i++) {
        const int a = a0 + i;
        const float4* w4 = (const float4*)(Wd + (size_t)a * HH);
        float s = 0.f;
        #pragma unroll
        for (int j = 0; j < 4; j++) {
            const float4 w = w4[lane + 32 * j];
            s += st[j].x * w.x + st[j].y * w.y + st[j].z * w.z + st[j].w * w.w;
        }
        #pragma unroll
        for (int o = 16; o; o >>= 1) s += __shfl_xor_sync(0xffffffffu, s, o);
        if (lane == 0) g_dec[b * AA + a] = s + bd[a] + be[a];
    }
}

// ======= K2b: pure bf16 mma.sync GEMM, 3-stage cp.async pipeline ==============
// Block: 128 s x 128 a, K=512 in 8 chunks of 64 bf16 (128 B/row, SW128).
// 8 warps: warp_s=wid&3 (32 rows), warp_a=wid>>2 (64 cols). 3 buffers per
// operand: during MMA on chunk c, chunks c+1 and c+2 are in flight.
#define K2_TILEB 16384
#define K2_W_OFF (3 * K2_TILEB)          // 49152
#define K2_SMEMB (6 * K2_TILEB + 2048)   // 100352

__device__ __forceinline__ void cp16(uint32_t daddr, const void* src) {
    asm volatile("cp.async.cg.shared.global [%0], [%1], 16;" :: "r"(daddr), "l"(src));
}
__device__ __forceinline__ void cp_commit() {
    asm volatile("cp.async.commit_group;" ::: "memory");
}
__device__ __forceinline__ void ldsm4(uint32_t* r, uint32_t addr) {
    asm volatile("ldmatrix.sync.aligned.m8n8.x4.shared.b16 {%0,%1,%2,%3}, [%4];"
                 : "=r"(r[0]), "=r"(r[1]), "=r"(r[2]), "=r"(r[3]) : "r"(addr));
}
__device__ __forceinline__ void mma_bf16(float* d, const uint32_t* a,
                                         uint32_t b0, uint32_t b1) {
    asm volatile(
        "mma.sync.aligned.m16n8k16.row.col.f32.bf16.bf16.f32 "
        "{%0,%1,%2,%3}, {%4,%5,%6,%7}, {%8,%9}, {%0,%1,%2,%3};"
        : "+f"(d[0]), "+f"(d[1]), "+f"(d[2]), "+f"(d[3])
        : "r"(a[0]), "r"(a[1]), "r"(a[2]), "r"(a[3]), "r"(b0), "r"(b1));
}

__global__ __launch_bounds__(256, 2) void k2b_scores(const float* __restrict__ Wv,
                                                     const float* __restrict__ bv) {
    extern __shared__ float sm[];
    const uint32_t smem_base = smem_u32(sm);
    float* sdec = sm + 24576;   // byte 98304
    float* swv  = sm + 24704;
    float* sp   = sm + 24832;   // 2*128 floats

    const int b  = blockIdx.y;
    const int s0 = blockIdx.x * 128;
    const int tid = threadIdx.x;
    const int lane = tid & 31;
    const int wid = tid >> 5;
    const int warp_s = wid & 3;
    const int warp_a = wid >> 2;
    const int ms = warp_s * 32;
    const int na = warp_a * 64;

    if (tid < 128) {
        sdec[tid] = g_dec[b * AA + tid];
        swv[tid]  = Wv[tid];
    }

    const char* encb = (const char*)g_enc_bf + ((size_t)b * SS + s0) * 1024;
    const char* web  = (const char*)g_We_bf;
    const int r_st  = tid >> 3;   // 0..31 (+32i)
    const int sg_st = tid & 7;    // 16B segment 0..7

    float acc[2][8][4];
    #pragma unroll
    for (int f = 0; f < 2; f++)
        #pragma unroll
        for (int g = 0; g < 8; g++)
            #pragma unroll
            for (int q = 0; q < 4; q++) acc[f][g][q] = 0.f;

    // one cp.async group per chunk: E(16KB) + W(16KB), 8 segs/thread
    auto issue = [&](int c) {
        const int buf = c % 3;
        #pragma unroll
        for (int i = 0; i < 4; i++) {
            const int r = r_st + i * 32;
            const uint32_t sw = (uint32_t)(r * 128 + ((sg_st ^ (r & 7)) << 4));
            cp16(smem_base + buf * K2_TILEB + sw,
                 encb + (size_t)r * 1024 + c * 128 + sg_st * 16);
            cp16(smem_base + K2_W_OFF + buf * K2_TILEB + sw,
                 web + (size_t)r * 1024 + c * 128 + sg_st * 16);
        }
        cp_commit();
    };

    issue(0); issue(1); issue(2);

    #pragma unroll
    for (int c = 0; c < 8; c++) {
        if (c <= 5)      asm volatile("cp.async.wait_group 2;" ::: "memory");
        else if (c == 6) asm volatile("cp.async.wait_group 1;" ::: "memory");
        else             asm volatile("cp.async.wait_group 0;" ::: "memory");
        __syncthreads();

        const uint32_t Eb = smem_base + (c % 3) * K2_TILEB;
        const uint32_t Wb = smem_base + K2_W_OFF + (c % 3) * K2_TILEB;
        #pragma unroll
        for (int ks = 0; ks < 4; ks++) {
            uint32_t afr[2][4];
            #pragma unroll
            for (int f = 0; f < 2; f++) {
                const int row = ms + f * 16 + (lane & 15);
                const int seg = ks * 2 + (lane >> 4);
                ldsm4(afr[f], Eb + row * 128 + ((seg ^ (row & 7)) << 4));
            }
            #pragma unroll
            for (int g2 = 0; g2 < 4; g2++) {
                const int row = na + g2 * 16 + ((lane >> 4) << 3) + (lane & 7);
                const int seg = ks * 2 + ((lane >> 3) & 1);
                uint32_t bfr[4];
                ldsm4(bfr, Wb + row * 128 + ((seg ^ (row & 7)) << 4));
                mma_bf16(acc[0][2 * g2],     afr[0], bfr[0], bfr[1]);
                mma_bf16(acc[0][2 * g2 + 1], afr[0], bfr[2], bfr[3]);
                mma_bf16(acc[1][2 * g2],     afr[1], bfr[0], bfr[1]);
                mma_bf16(acc[1][2 * g2 + 1], afr[1], bfr[2], bfr[3]);
            }
        }
        __syncthreads();
        if (c < 5) issue(c + 3);
    }

    // epilogue: tanh(acc + dec) * wv, reduce over a
    #pragma unroll
    for (int f = 0; f < 2; f++) {
        float pl = 0.f, ph = 0.f;
        #pragma unroll
        for (int g = 0; g < 8; g++) {
            const int a0 = warp_a * 64 + g * 8 + (lane & 3) * 2;
            const float d0 = sdec[a0], d1 = sdec[a0 + 1];
            const float w0 = swv[a0],  w1 = swv[a0 + 1];
            pl += fast_tanh(acc[f][g][0] + d0) * w0 + fast_tanh(acc[f][g][1] + d1) * w1;
            ph += fast_tanh(acc[f][g][2] + d0) * w0 + fast_tanh(acc[f][g][3] + d1) * w1;
        }
        pl += __shfl_xor_sync(0xffffffffu, pl, 1);
        pl += __shfl_xor_sync(0xffffffffu, pl, 2);
        ph += __shfl_xor_sync(0xffffffffu, ph, 1);
        ph += __shfl_xor_sync(0xffffffffu, ph, 2);
        if ((lane & 3) == 0) {
            const int sl = ms + f * 16 + (lane >> 2);
            sp[warp_a * 128 + sl]     = pl;
            sp[warp_a * 128 + sl + 8] = ph;
        }
    }
    __syncthreads();
    if (tid < 128)
        g_scores[b * SS + s0 + tid] = sp[tid] + sp[128 + tid] + bv[0];
}

// ---------------- K3a: softmax over seq per batch (+ zero g_att) --------------
// grid BB, block 1024: one element per thread, shuffle reductions.
__global__ __launch_bounds__(1024) void k3a_softmax() {
    const int b = blockIdx.x, tid = threadIdx.x;
    const int lane = tid & 31, warp = tid >> 5;
    __shared__ float red[32];
    __shared__ float bcast;

    if (tid < HH) g_att[b * HH + tid] = 0.f;

    float v = g_scores[b * SS + tid];

    // --- max ---
    float m = v;
    #pragma unroll
    for (int o = 16; o; o >>= 1) m = fmaxf(m, __shfl_xor_sync(0xffffffffu, m, o));
    if (lane == 0) red[warp] = m;
    __syncthreads();
    if (warp == 0) {
        float t = red[lane];
        #pragma unroll
        for (int o = 16; o; o >>= 1) t = fmaxf(t, __shfl_xor_sync(0xffffffffu, t, o));
        if (lane == 0) bcast = t;
    }
    __syncthreads();
    const float mx = bcast;

    // --- sum ---
    const float e = expf(v - mx);
    float s = e;
    #pragma unroll
    for (int o = 16; o; o >>= 1) s += __shfl_xor_sync(0xffffffffu, s, o);
    __syncthreads();
    if (lane == 0) red[warp] = s;
    __syncthreads();
    if (warp == 0) {
        float t = red[lane];
        #pragma unroll
        for (int o = 16; o; o >>= 1) t += __shfl_xor_sync(0xffffffffu, t, o);
        if (lane == 0) bcast = 1.f / t;
    }
    __syncthreads();
    g_probs[b * SS + tid] = e * bcast;
}

// ---------------- K3b: attention from bf16 enc (L2-resident) ------------------
// grid (HH/128=4, SS/256=4, BB), 256 threads; each thread: 4 h via uint2 loads.
__global__ __launch_bounds__(256) void k3b_att() {
    const int b  = blockIdx.z;
    const int sb = blockIdx.y;
    const int hb = blockIdx.x;
    const int lane = threadIdx.x & 31;
    const int srow = threadIdx.x >> 5;
    const uint2* e = (const uint2*)g_enc_bf
                   + ((size_t)b * SS + sb * 256 + srow) * 128 + hb * 32 + lane;
    const float* pr = g_probs + b * SS + sb * 256 + srow;

    float4 a0 = {0.f, 0.f, 0.f, 0.f}, a1 = {0.f, 0.f, 0.f, 0.f};
    #pragma unroll 4
    for (int i = 0; i < 32; i += 2) {
        const float p0 = pr[i * 8];
        const float p1 = pr[(i + 1) * 8];
        const uint2 u0 = e[(size_t)i * 8 * 128];
        const uint2 u1 = e[(size_t)(i + 1) * 8 * 128];
        a0.x = fmaf(p0, bf_lo(u0.x), a0.x); a0.y = fmaf(p0, bf_hi(u0.x), a0.y);
        a0.z = fmaf(p0, bf_lo(u0.y), a0.z); a0.w = fmaf(p0, bf_hi(u0.y), a0.w);
        a1.x = fmaf(p1, bf_lo(u1.x), a1.x); a1.y = fmaf(p1, bf_hi(u1.x), a1.y);
        a1.z = fmaf(p1, bf_lo(u1.y), a1.z); a1.w = fmaf(p1, bf_hi(u1.y), a1.w);
    }
    a0.x += a1.x; a0.y += a1.y; a0.z += a1.z; a0.w += a1.w;

    __shared__ float red[8][32][4];
    red[srow][lane][0] = a0.x;
    red[srow][lane][1] = a0.y;
    red[srow][lane][2] = a0.z;
    red[srow][lane][3] = a0.w;
    __syncthreads();
    if (threadIdx.x < 128) {
        const int l = threadIdx.x & 31;
        const int comp = threadIdx.x >> 5;
        float s = 0.f;
        #pragma unroll
        for (int r = 0; r < 8; r++) s += red[r][l][comp];
        atomicAdd(&g_att[b * HH + hb * 128 + l * 4 + comp], s);
    }
}

// ---------------- K4: gate GEMMs, phase x K-half split, partial buffers -------
// grid (96, 4): y>>1 = phase (0: gi, 1: gh), y&1 = K-half. No atomics:
// each (phase, half) writes its own partial buffer; k5 sums them + biases.
__global__ __launch_bounds__(256) void k4_gemm(const float* __restrict__ inputs,
                                               const float* __restrict__ states,
                                               const float* __restrict__ W_ih,
                                               const float* __restrict__ W_hh) {
    const int j0 = blockIdx.x * 16;
    const int phase = blockIdx.y >> 1;
    const int half  = blockIdx.y & 1;
    const int tid = threadIdx.x;
    const int tx = tid & 15;
    const int tb = tid >> 4;
    const int j = j0 + tx;
    __shared__ float Xs[64][65];
    __shared__ float Wsm[64][17];

    float acc[4] = {0.f, 0.f, 0.f, 0.f};
    if (phase == 0) {
        const int kbeg = half * 384, kend = kbeg + 384;
        for (int k0 = kbeg; k0 < kend; k0 += 64) {
            #pragma unroll
            for (int it = 0; it < 16; it++) {
                int idx = it * 256 + tid;
                int bb = idx >> 6, k = idx & 63;
                int kg = k0 + k;
                Xs[k][bb] = (kg < DD) ? inputs[bb * DD + kg]
                                      : g_att[bb * HH + (kg - DD)];
            }
            #pragma unroll
            for (int it = 0; it < 4; it++) {
                int idx = it * 256 + tid;
                int jj = idx >> 6, k = idx & 63;
                Wsm[k][jj] = W_ih[(j0 + jj) * (DD + HH) + k0 + k];
            }
            __syncthreads();
            #pragma unroll
            for (int k = 0; k < 64; k++) {
                float w = Wsm[k][tx];
                #pragma unroll
                for (int i = 0; i < 4; i++)
                    acc[i] = fmaf(Xs[k][tb + 16 * i], w, acc[i]);
            }
            __syncthreads();
        }
        float* dst = half ? g_p1 : g_p0;
        #pragma unroll
        for (int i = 0; i < 4; i++)
            dst[(tb + 16 * i) * H3 + j] = acc[i];
    } else {
        const int kbeg = half * 256, kend = kbeg + 256;
        for (int k0 = kbeg; k0 < kend; k0 += 64) {
            #pragma unroll
            for (int it = 0; it < 16; it++) {
                int idx = it * 256 + tid;
                int bb = idx >> 6, k = idx & 63;
                Xs[k][bb] = states[bb * HH + k0 + k];
            }
            #pragma unroll
            for (int it = 0; it < 4; it++) {
                int idx = it * 256 + tid;
                int jj = idx >> 6, k = idx & 63;
                Wsm[k][jj] = W_hh[(j0 + jj) * HH + k0 + k];
            }
            __syncthreads();
            #pragma unroll
            for (int k = 0; k < 64; k++) {
                float w = Wsm[k][tx];
                #pragma unroll
                for (int i = 0; i < 4; i++)
                    acc[i] = fmaf(Xs[k][tb + 16 * i], w, acc[i]);
            }
            __syncthreads();
        }
        float* dst = half ? g_q1 : g_q0;
        #pragma unroll
        for (int i = 0; i < 4; i++)
            dst[(tb + 16 * i) * H3 + j] = acc[i];
    }
}

// ---------------- K5: GRU gates + output (sum partials + biases) --------------
__global__ void k5_gru(const float* __restrict__ states,
                       const float* __restrict__ b_ih,
                       const float* __restrict__ b_hh,
                       float* __restrict__ out) {
    const int b = blockIdx.x, h = threadIdx.x;
    const int o0 = b * H3 + h, o1 = o0 + HH, o2 = o1 + HH;
    const float ir = g_p0[o0] + g_p1[o0] + b_ih[h];
    const float iz = g_p0[o1] + g_p1[o1] + b_ih[HH + h];
    const float in_ = g_p0[o2] + g_p1[o2] + b_ih[2 * HH + h];
    const float hr = g_q0[o0] + g_q1[o0] + b_hh[h];
    const float hz = g_q0[o1] + g_q1[o1] + b_hh[HH + h];
    const float hn = g_q0[o2] + g_q1[o2] + b_hh[2 * HH + h];
    const float r = 1.f / (1.f + expf(-(ir + hr)));
    const float z = 1.f / (1.f + expf(-(iz + hz)));
    const float n = tanhf(in_ + r * hn);
    out[b * HH + h] = (1.f - z) * n + z * states[b * HH + h];
}

// ---------------- launch ------------------------------------------------------
extern "C" void kernel_launch(void* const* d_in, const int* in_sizes, int n_in,
                              void* d_out, int out_size) {
    const float* encoded = (const float*)d_in[0];
    const float* inputs  = (const float*)d_in[1];
    const float* states  = (const float*)d_in[2];
    const float* We      = (const float*)d_in[3];
    const float* be      = (const float*)d_in[4];
    const float* Wd      = (const float*)d_in[5];
    const float* bd      = (const float*)d_in[6];
    const float* Wv      = (const float*)d_in[7];
    const float* bv      = (const float*)d_in[8];
    const float* W_ih    = (const float*)d_in[9];
    const float* W_hh    = (const float*)d_in[10];
    const float* b_ih    = (const float*)d_in[11];
    const float* b_hh    = (const float*)d_in[12];
    float* out = (float*)d_out;

    cudaFuncSetAttribute(k2b_scores, cudaFuncAttributeMaxDynamicSharedMemorySize,
                         K2_SMEMB);

    k0_convW<<<32, 256>>>(We);
    k2a_conv<<<BB * SS * HH / (256 * 16), 256>>>(encoded);
    k1_decproj<<<dim3(BB, 8), 128>>>(states, Wd, bd, be);
    k2b_scores<<<dim3(SS / 128, BB), 256, K2_SMEMB>>>(Wv, bv);
    k3a_softmax<<<BB, 1024>>>();
    k3b_att<<<dim3(HH / 128, SS / 256, BB), 256>>>();
    k4_gemm<<<dim3(H3 / 16, 4), 256>>>(inputs, states, W_ih, W_hh);
    k5_gru<<<BB, 512>>>(states, b_ih, b_hh, out);
}